// round 5
// baseline (speedup 1.0000x reference)
#include <cuda_runtime.h>
#include <cuda_bf16.h>
#include <cstdint>
#include <cstddef>

#define D_MODEL 512
#define NHEAD   8
#define DH      64
#define BATCH   2
#define SEQ     2048
#define NTOK    (BATCH*SEQ)   // 4096
#define NBH     (BATCH*NHEAD) // 16
#define N1      (NTOK*D_MODEL)     // 2,097,152
#define N2      (D_MODEL*D_MODEL)  // 262,144

static const int       OUT_ELEMS  = N1;
static const long long ATTN_ELEMS = (long long)NBH*SEQ*SEQ;

// ---------------- device scratch (allocation-free rule) ----------------
__device__ __align__(16) __nv_bfloat16 g_INh[3*N1], g_INl[3*N1];
__device__ __align__(16) __nv_bfloat16 g_Wh[4*N2],  g_Wl[4*N2];
__device__ __align__(16) __nv_bfloat16 g_Qh[NBH*SEQ*DH], g_Ql[NBH*SEQ*DH];
__device__ __align__(16) __nv_bfloat16 g_Kh[NBH*SEQ*DH], g_Kl[NBH*SEQ*DH];
__device__ __align__(16) __nv_bfloat16 g_Vth[NBH*DH*SEQ], g_Vtl[NBH*DH*SEQ];
__device__ __align__(16) __nv_bfloat16 g_Xh[N1], g_Xl[N1];
__device__ __align__(16) float         g_attn_fallback[(size_t)NBH*SEQ*SEQ];

// ---------------- helpers ----------------
__device__ __forceinline__ uint32_t smem_u32(const void* p) {
    uint32_t a;
    asm("{ .reg .u64 t; cvta.to.shared.u64 t, %1; cvt.u32.u64 %0, t; }" : "=r"(a) : "l"(p));
    return a;
}
__device__ __forceinline__ void bf16_split(float v, __nv_bfloat16& hi, __nv_bfloat16& lo) {
    hi = __float2bfloat16(v);
    lo = __float2bfloat16(v - __bfloat162float(hi));
}
__device__ __forceinline__ uint32_t pack2(__nv_bfloat16 a, __nv_bfloat16 b) {
    return (uint32_t)__bfloat16_as_ushort(a) | ((uint32_t)__bfloat16_as_ushort(b) << 16);
}
__device__ __forceinline__ void mma_bf16(float d[4], const uint32_t a[4], const uint32_t b[2]) {
    asm volatile(
        "mma.sync.aligned.m16n8k16.row.col.f32.bf16.bf16.f32 "
        "{%0,%1,%2,%3}, {%4,%5,%6,%7}, {%8,%9}, {%0,%1,%2,%3};\n"
        : "+f"(d[0]), "+f"(d[1]), "+f"(d[2]), "+f"(d[3])
        : "r"(a[0]), "r"(a[1]), "r"(a[2]), "r"(a[3]), "r"(b[0]), "r"(b[1]));
}

#define TSTRIDE_B 144
#define TILE_BYTES (128*TSTRIDE_B)    // 18432
#define BTILE64    (64*TSTRIDE_B)     // 9216

#define CP_COMMIT() asm volatile("cp.async.commit_group;" ::: "memory")

__device__ __forceinline__ void cp_tile128(char* dst, const __nv_bfloat16* src, int ld, int tid) {
    const int row = tid >> 3, c = tid & 7;
#pragma unroll
    for (int t = 0; t < 4; t++) {
        uint32_t d = smem_u32(dst + (row + t*32)*TSTRIDE_B + c*16);
        const void* g = src + (size_t)(row + t*32)*ld + c*8;
        asm volatile("cp.async.cg.shared.global [%0], [%1], 16;" :: "r"(d), "l"(g) : "memory");
    }
}
__device__ __forceinline__ void cp_tile64(char* dst, const __nv_bfloat16* src, int ld, int tid) {
    const int row = tid >> 3, c = tid & 7;
#pragma unroll
    for (int t = 0; t < 2; t++) {
        uint32_t d = smem_u32(dst + (row + t*32)*TSTRIDE_B + c*16);
        const void* g = src + (size_t)(row + t*32)*ld + c*8;
        asm volatile("cp.async.cg.shared.global [%0], [%1], 16;" :: "r"(d), "l"(g) : "memory");
    }
}

template<int NT>
__device__ __forceinline__ void hmma_3pass(
    const char* A0, const char* A1, const char* B0, const char* B1,
    int i0w, int j0w, int gid, int tig, float acc[2][NT][4])
{
#pragma unroll
    for (int pass = 0; pass < 3; pass++) {
        const char* A = (pass == 2) ? A1 : A0;
        const char* B = (pass == 1) ? B1 : B0;
#pragma unroll
        for (int ks = 0; ks < 4; ks++) {
            const int kb = (ks*16 + tig*2) * 2;
            uint32_t a[2][4];
#pragma unroll
            for (int mt = 0; mt < 2; mt++) {
                const char* base = A + (i0w + mt*16 + gid)*TSTRIDE_B + kb;
                a[mt][0] = *reinterpret_cast<const uint32_t*>(base);
                a[mt][1] = *reinterpret_cast<const uint32_t*>(base + 8*TSTRIDE_B);
                a[mt][2] = *reinterpret_cast<const uint32_t*>(base + 16);
                a[mt][3] = *reinterpret_cast<const uint32_t*>(base + 8*TSTRIDE_B + 16);
            }
#pragma unroll
            for (int nt = 0; nt < NT; nt++) {
                const char* base = B + (j0w + nt*8 + gid)*TSTRIDE_B + kb;
                uint32_t bb[2];
                bb[0] = *reinterpret_cast<const uint32_t*>(base);
                bb[1] = *reinterpret_cast<const uint32_t*>(base + 16);
                mma_bf16(acc[0][nt], a[0], bb);
                mma_bf16(acc[1][nt], a[1], bb);
            }
        }
    }
}

// ---------------------------------------------------------------------------
// Split kernel: fp32 -> bf16 hi/lo for 3 inputs + 4 weight matrices
// ---------------------------------------------------------------------------
__global__ void __launch_bounds__(256)
split_kernel(const float* __restrict__ q, const float* __restrict__ k, const float* __restrict__ v,
             const float* __restrict__ Wq, const float* __restrict__ Wk,
             const float* __restrict__ Wv, const float* __restrict__ Wo)
{
    const int which = blockIdx.y;
    const float* src; __nv_bfloat16* dh; __nv_bfloat16* dl; int count;
    if (which < 3) {
        src = (which == 0) ? q : (which == 1) ? k : v;
        dh = g_INh + (size_t)which*N1; dl = g_INl + (size_t)which*N1; count = N1/4;
    } else {
        const int w = which - 3;
        src = (w == 0) ? Wq : (w == 1) ? Wk : (w == 2) ? Wv : Wo;
        dh = g_Wh + (size_t)w*N2; dl = g_Wl + (size_t)w*N2; count = N2/4;
    }
    for (int i = blockIdx.x*blockDim.x + threadIdx.x; i < count; i += gridDim.x*blockDim.x) {
        float4 x = reinterpret_cast<const float4*>(src)[i];
        __nv_bfloat16 h0,l0,h1,l1,h2,l2,h3,l3;
        bf16_split(x.x,h0,l0); bf16_split(x.y,h1,l1);
        bf16_split(x.z,h2,l2); bf16_split(x.w,h3,l3);
        uint2 ph, pl;
        ph.x = pack2(h0,h1); ph.y = pack2(h2,h3);
        pl.x = pack2(l0,l1); pl.y = pack2(l2,l3);
        reinterpret_cast<uint2*>(dh)[i] = ph;
        reinterpret_cast<uint2*>(dl)[i] = pl;
    }
}

// ---------------------------------------------------------------------------
// QKV projection: HMMA split, 128x128 tile, K=512 (8 chunks), cp.async 2-deep.
// ---------------------------------------------------------------------------
#define PROJ_SMEM (8*TILE_BYTES)   // 147456
__global__ void __launch_bounds__(256)
qkv_proj_kernel(const float* __restrict__ bq, const float* __restrict__ bk,
                const float* __restrict__ bv)
{
    extern __shared__ char smem[];
    const int tid = threadIdx.x, wid = tid >> 5, lane = tid & 31;
    const int gid = lane >> 2, tig = lane & 3;
    const int z = blockIdx.z;
    const int m0 = blockIdx.y*128, n0 = blockIdx.x*128;
    const int i0w = (wid & 3)*32, j0w = (wid >> 2)*64;

    const __nv_bfloat16* Ah = g_INh + (size_t)z*N1 + (size_t)m0*D_MODEL;
    const __nv_bfloat16* Al = g_INl + (size_t)z*N1 + (size_t)m0*D_MODEL;
    const __nv_bfloat16* Bh = g_Wh  + (size_t)z*N2 + (size_t)n0*D_MODEL;
    const __nv_bfloat16* Bl = g_Wl  + (size_t)z*N2 + (size_t)n0*D_MODEL;
    const float* bias = (z == 0) ? bq : (z == 1) ? bk : bv;

    float acc[2][8][4];
#pragma unroll
    for (int mt = 0; mt < 2; mt++)
#pragma unroll
        for (int nt = 0; nt < 8; nt++)
#pragma unroll
            for (int q = 0; q < 4; q++) acc[mt][nt][q] = 0.f;

    {
        char* buf = smem;
        cp_tile128(buf,                Ah, D_MODEL, tid);
        cp_tile128(buf +   TILE_BYTES, Al, D_MODEL, tid);
        cp_tile128(buf + 2*TILE_BYTES, Bh, D_MODEL, tid);
        cp_tile128(buf + 3*TILE_BYTES, Bl, D_MODEL, tid);
        CP_COMMIT();
    }
    for (int ch = 0; ch < 8; ch++) {
        if (ch < 7) {
            char* buf = smem + ((ch+1)&1)*(4*TILE_BYTES);
            const int k0 = (ch+1)*64;
            cp_tile128(buf,                Ah + k0, D_MODEL, tid);
            cp_tile128(buf +   TILE_BYTES, Al + k0, D_MODEL, tid);
            cp_tile128(buf + 2*TILE_BYTES, Bh + k0, D_MODEL, tid);
            cp_tile128(buf + 3*TILE_BYTES, Bl + k0, D_MODEL, tid);
            CP_COMMIT();
            asm volatile("cp.async.wait_group 1;" ::: "memory");
        } else {
            asm volatile("cp.async.wait_group 0;" ::: "memory");
        }
        __syncthreads();
        char* buf = smem + (ch&1)*(4*TILE_BYTES);
        hmma_3pass<8>(buf, buf + TILE_BYTES, buf + 2*TILE_BYTES, buf + 3*TILE_BYTES,
                      i0w, j0w, gid, tig, acc);
        __syncthreads();
    }

#pragma unroll
    for (int nt = 0; nt < 8; nt++) {
        const int col = n0 + j0w + nt*8 + tig*2;
        const int h = col >> 6, d = col & 63;
        const float b0v = bias[col], b1v = bias[col+1];
#pragma unroll
        for (int mt = 0; mt < 2; mt++) {
#pragma unroll
            for (int half = 0; half < 2; half++) {
                const int token = m0 + i0w + mt*16 + gid + half*8;
                const int b = token >> 11, s = token & 2047;
                float v0 = acc[mt][nt][half*2+0] + b0v;
                float v1 = acc[mt][nt][half*2+1] + b1v;
                __nv_bfloat16 h0,l0,h1,l1;
                bf16_split(v0,h0,l0); bf16_split(v1,h1,l1);
                if (z == 0) {
                    size_t o = ((size_t)(b*NHEAD + h)*SEQ + s)*DH + d;
                    *reinterpret_cast<uint32_t*>(g_Qh + o) = pack2(h0,h1);
                    *reinterpret_cast<uint32_t*>(g_Ql + o) = pack2(l0,l1);
                } else if (z == 1) {
                    size_t o = ((size_t)(b*NHEAD + h)*SEQ + s)*DH + d;
                    *reinterpret_cast<uint32_t*>(g_Kh + o) = pack2(h0,h1);
                    *reinterpret_cast<uint32_t*>(g_Kl + o) = pack2(l0,l1);
                } else {
                    size_t o0 = ((size_t)(b*NHEAD + h)*DH + d)*SEQ + s;
                    g_Vth[o0] = h0; g_Vtl[o0] = l0;
                    g_Vth[o0 + SEQ] = h1; g_Vtl[o0 + SEQ] = l1;
                }
            }
        }
    }
}

// ---------------------------------------------------------------------------
// Output projection
// ---------------------------------------------------------------------------
__global__ void __launch_bounds__(256)
oproj_kernel(const float* __restrict__ bo, float* __restrict__ out)
{
    extern __shared__ char smem[];
    const int tid = threadIdx.x, wid = tid >> 5, lane = tid & 31;
    const int gid = lane >> 2, tig = lane & 3;
    const int m0 = blockIdx.y*128, n0 = blockIdx.x*128;
    const int i0w = (wid & 3)*32, j0w = (wid >> 2)*64;

    const __nv_bfloat16* Ah = g_Xh + (size_t)m0*D_MODEL;
    const __nv_bfloat16* Al = g_Xl + (size_t)m0*D_MODEL;
    const __nv_bfloat16* Bh = g_Wh + (size_t)3*N2 + (size_t)n0*D_MODEL;
    const __nv_bfloat16* Bl = g_Wl + (size_t)3*N2 + (size_t)n0*D_MODEL;

    float acc[2][8][4];
#pragma unroll
    for (int mt = 0; mt < 2; mt++)
#pragma unroll
        for (int nt = 0; nt < 8; nt++)
#pragma unroll
            for (int q = 0; q < 4; q++) acc[mt][nt][q] = 0.f;

    {
        char* buf = smem;
        cp_tile128(buf,                Ah, D_MODEL, tid);
        cp_tile128(buf +   TILE_BYTES, Al, D_MODEL, tid);
        cp_tile128(buf + 2*TILE_BYTES, Bh, D_MODEL, tid);
        cp_tile128(buf + 3*TILE_BYTES, Bl, D_MODEL, tid);
        CP_COMMIT();
    }
    for (int ch = 0; ch < 8; ch++) {
        if (ch < 7) {
            char* buf = smem + ((ch+1)&1)*(4*TILE_BYTES);
            const int k0 = (ch+1)*64;
            cp_tile128(buf,                Ah + k0, D_MODEL, tid);
            cp_tile128(buf +   TILE_BYTES, Al + k0, D_MODEL, tid);
            cp_tile128(buf + 2*TILE_BYTES, Bh + k0, D_MODEL, tid);
            cp_tile128(buf + 3*TILE_BYTES, Bl + k0, D_MODEL, tid);
            CP_COMMIT();
            asm volatile("cp.async.wait_group 1;" ::: "memory");
        } else {
            asm volatile("cp.async.wait_group 0;" ::: "memory");
        }
        __syncthreads();
        char* buf = smem + (ch&1)*(4*TILE_BYTES);
        hmma_3pass<8>(buf, buf + TILE_BYTES, buf + 2*TILE_BYTES, buf + 3*TILE_BYTES,
                      i0w, j0w, gid, tig, acc);
        __syncthreads();
    }

#pragma unroll
    for (int nt = 0; nt < 8; nt++) {
        const int col = n0 + j0w + nt*8 + tig*2;
        const float b0v = bo[col], b1v = bo[col+1];
#pragma unroll
        for (int mt = 0; mt < 2; mt++) {
#pragma unroll
            for (int half = 0; half < 2; half++) {
                const int row = m0 + i0w + mt*16 + gid + half*8;
                float2 o;
                o.x = acc[mt][nt][half*2+0] + b0v;
                o.y = acc[mt][nt][half*2+1] + b1v;
                *reinterpret_cast<float2*>(out + (size_t)row*D_MODEL + col) = o;
            }
        }
    }
}

// ---------------------------------------------------------------------------
// Fused score+softmax: CTA = 16 query rows x full 2048 cols, one bh.
// Scores in smem (16 x 2052 fp32), K streamed in 128-col chunks (2-deep).
// Writes final normalized attn fp32 ONCE.
// ---------------------------------------------------------------------------
#define SROW     2052                 // padded row stride in floats
#define QT_BYTES (16*TSTRIDE_B)       // 2304
#define KCH      (128*TSTRIDE_B)      // 18432
#define KBUF     (2*KCH)              // 36864
#define FS_Q     (16*SROW*4)          // 131328
#define FS_K     (FS_Q + 2*QT_BYTES)  // 135936
#define FUSED_SMEM (FS_K + 2*KBUF)    // 209664

__global__ void __launch_bounds__(256)
fused_attn_kernel(const int* __restrict__ mask, float* attn_arg)
{
    float* attn = attn_arg ? attn_arg : g_attn_fallback;
    extern __shared__ char smem[];
    float* S = reinterpret_cast<float*>(smem);
    char* sQ = smem + FS_Q;

    const int tid = threadIdx.x, wid = tid >> 5, lane = tid & 31;
    const int gid = lane >> 2, tig = lane & 3;
    const int bh = blockIdx.y, b = bh >> 3;
    const int m0 = blockIdx.x * 16;

    // Q tile load: 16 rows x 64 bf16, hi+lo (one 16B cp per thread)
    {
        const int which = tid >> 7;
        const int r = (tid & 127) >> 3, c = tid & 7;
        const __nv_bfloat16* src = which ? g_Ql : g_Qh;
        uint32_t d = smem_u32(sQ + which*QT_BYTES + r*TSTRIDE_B + c*16);
        const void* g = src + ((size_t)bh*SEQ + m0 + r)*DH + c*8;
        asm volatile("cp.async.cg.shared.global [%0], [%1], 16;" :: "r"(d), "l"(g) : "memory");
    }
    // K chunk 0,1
    {
        char* kb = smem + FS_K;
        cp_tile128(kb,       g_Kh + (size_t)bh*SEQ*DH, DH, tid);
        cp_tile128(kb + KCH, g_Kl + (size_t)bh*SEQ*DH, DH, tid);
        CP_COMMIT();
        kb = smem + FS_K + KBUF;
        cp_tile128(kb,       g_Kh + ((size_t)bh*SEQ + 128)*DH, DH, tid);
        cp_tile128(kb + KCH, g_Kl + ((size_t)bh*SEQ + 128)*DH, DH, tid);
        CP_COMMIT();
    }

    for (int ch = 0; ch < 16; ch++) {
        if (ch < 14) asm volatile("cp.async.wait_group 1;" ::: "memory");
        else         asm volatile("cp.async.wait_group 0;" ::: "memory");
        __syncthreads();

        const char* A0 = sQ;
        const char* A1 = sQ + QT_BYTES;
        const char* K0 = smem + FS_K + (ch&1)*KBUF;
        const char* K1 = K0 + KCH;

        float acc[2][4];
#pragma unroll
        for (int nt = 0; nt < 2; nt++)
#pragma unroll
            for (int q = 0; q < 4; q++) acc[nt][q] = 0.f;

#pragma unroll
        for (int pass = 0; pass < 3; pass++) {
            const char* A = (pass == 2) ? A1 : A0;
            const char* B = (pass == 1) ? K1 : K0;
#pragma unroll
            for (int ks = 0; ks < 4; ks++) {
                const int kb = (ks*16 + tig*2) * 2;
                uint32_t a[4];
                {
                    const char* base = A + gid*TSTRIDE_B + kb;
                    a[0] = *reinterpret_cast<const uint32_t*>(base);
                    a[1] = *reinterpret_cast<const uint32_t*>(base + 8*TSTRIDE_B);
                    a[2] = *reinterpret_cast<const uint32_t*>(base + 16);
                    a[3] = *reinterpret_cast<const uint32_t*>(base + 8*TSTRIDE_B + 16);
                }
#pragma unroll
                for (int nt = 0; nt < 2; nt++) {
                    const char* base = B + (wid*16 + nt*8 + gid)*TSTRIDE_B + kb;
                    uint32_t bb[2];
                    bb[0] = *reinterpret_cast<const uint32_t*>(base);
                    bb[1] = *reinterpret_cast<const uint32_t*>(base + 16);
                    mma_bf16(acc[nt], a, bb);
                }
            }
        }

        // store scores into S with scale + mask
#pragma unroll
        for (int nt = 0; nt < 2; nt++) {
            const int col = ch*128 + wid*16 + nt*8 + tig*2;
            const int mv0 = __ldg(mask + b*SEQ + col);
            const int mv1 = __ldg(mask + b*SEQ + col + 1);
#pragma unroll
            for (int half = 0; half < 2; half++) {
                const int rl = gid + half*8;
                float v0 = acc[nt][half*2+0] * 0.125f;
                float v1 = acc[nt][half*2+1] * 0.125f;
                if (mv0 == 0) v0 = -1.0e9f;
                if (mv1 == 0) v1 = -1.0e9f;
                float2 o; o.x = v0; o.y = v1;
                *reinterpret_cast<float2*>(S + rl*SROW + col) = o;
            }
        }
        __syncthreads();
        if (ch < 14) {
            char* kb = smem + FS_K + (ch&1)*KBUF;
            cp_tile128(kb,       g_Kh + ((size_t)bh*SEQ + (ch+2)*128)*DH, DH, tid);
            cp_tile128(kb + KCH, g_Kl + ((size_t)bh*SEQ + (ch+2)*128)*DH, DH, tid);
            CP_COMMIT();
        }
    }

    // ---- softmax over each row (16 threads per row) ----
    const int rrow = tid >> 4, rj = tid & 15;
    float* Srow = S + rrow*SROW;

    float m = -3.0e38f;
#pragma unroll 8
    for (int i = 0; i < 32; i++) {
        float4 v = *reinterpret_cast<float4*>(Srow + 4*rj + 64*i);
        m = fmaxf(m, fmaxf(fmaxf(v.x, v.y), fmaxf(v.z, v.w)));
    }
#pragma unroll
    for (int o = 8; o; o >>= 1) m = fmaxf(m, __shfl_xor_sync(0xffffffffu, m, o));

    float s = 0.f;
#pragma unroll 8
    for (int i = 0; i < 32; i++) {
        float4 v = *reinterpret_cast<float4*>(Srow + 4*rj + 64*i);
        v.x = __expf(v.x - m); v.y = __expf(v.y - m);
        v.z = __expf(v.z - m); v.w = __expf(v.w - m);
        s += v.x + v.y + v.z + v.w;
        *reinterpret_cast<float4*>(Srow + 4*rj + 64*i) = v;
    }
#pragma unroll
    for (int o = 8; o; o >>= 1) s += __shfl_xor_sync(0xffffffffu, s, o);
    const float inv = 1.0f / s;

    float* dst = attn + ((size_t)bh*SEQ + m0 + rrow)*SEQ;
#pragma unroll 8
    for (int i = 0; i < 32; i++) {
        float4 v = *reinterpret_cast<float4*>(Srow + 4*rj + 64*i);
        v.x *= inv; v.y *= inv; v.z *= inv; v.w *= inv;
        *reinterpret_cast<float4*>(dst + 4*rj + 64*i) = v;
    }
}

// ---------------------------------------------------------------------------
// PV kernel: A = attn fp32 (split to bf16 hi/lo inline), V via cp.async.
// 128(i) x 64(d) per CTA, K=2048 in 32 chunks, both operands 2-deep.
// ---------------------------------------------------------------------------
#define PVBUFA (2*TILE_BYTES)              // 36864 per buffer (hi+lo)
#define PVBUFV (2*BTILE64)                 // 18432 per buffer
#define PV_SMEM (2*PVBUFA + 2*PVBUFV)      // 110592
__global__ void __launch_bounds__(256)
pv_kernel(const float* attn_arg)
{
    const float* attn = attn_arg ? attn_arg : g_attn_fallback;
    extern __shared__ char smem[];
    const int tid = threadIdx.x, wid = tid >> 5, lane = tid & 31;
    const int gid = lane >> 2, tig = lane & 3;
    const int bh = blockIdx.y, b = bh >> 3, h = bh & 7;
    const int m0 = blockIdx.x * 128;
    const int i0w = (wid & 3)*32, d0w = (wid >> 2)*32;

    const float* Asrc = attn + ((size_t)bh*SEQ + m0)*SEQ;
    const __nv_bfloat16* Bh = g_Vth + (size_t)bh*DH*SEQ;
    const __nv_bfloat16* Bl = g_Vtl + (size_t)bh*DH*SEQ;

    const int arow = tid >> 1, ahalf = tid & 1;     // each thread: 1 row, 32 cols

    float acc[2][4][4];
#pragma unroll
    for (int mt = 0; mt < 2; mt++)
#pragma unroll
        for (int nt = 0; nt < 4; nt++)
#pragma unroll
            for (int q = 0; q < 4; q++) acc[mt][nt][q] = 0.f;

    float4 fA[8];
#pragma unroll
    for (int q = 0; q < 8; q++)
        fA[q] = *reinterpret_cast<const float4*>(Asrc + (size_t)arow*SEQ + ahalf*32 + q*4);

    // V chunks 0,1
    {
        char* vb = smem + 2*PVBUFA;
        cp_tile64(vb,           Bh, SEQ, tid);
        cp_tile64(vb + BTILE64, Bl, SEQ, tid);
        CP_COMMIT();
        vb = smem + 2*PVBUFA + PVBUFV;
        cp_tile64(vb,           Bh + 64, SEQ, tid);
        cp_tile64(vb + BTILE64, Bl + 64, SEQ, tid);
        CP_COMMIT();
    }

    for (int ch = 0; ch < 32; ch++) {
        if (ch < 30) asm volatile("cp.async.wait_group 1;" ::: "memory");
        else         asm volatile("cp.async.wait_group 0;" ::: "memory");

        // split staged fp32 A into bf16 hi/lo smem tiles
        char* ab = smem + (ch&1)*PVBUFA;
#pragma unroll
        for (int q = 0; q < 4; q++) {
            float f[8] = { fA[2*q].x, fA[2*q].y, fA[2*q].z, fA[2*q].w,
                           fA[2*q+1].x, fA[2*q+1].y, fA[2*q+1].z, fA[2*q+1].w };
            uint32_t ph[4], pl[4];
#pragma unroll
            for (int e = 0; e < 4; e++) {
                __nv_bfloat16 h0,l0,h1,l1;
                bf16_split(f[2*e],   h0, l0);
                bf16_split(f[2*e+1], h1, l1);
                ph[e] = pack2(h0, h1);
                pl[e] = pack2(l0, l1);
            }
            const int boff = arow*TSTRIDE_B + ahalf*64 + q*16;
            *reinterpret_cast<uint4*>(ab + boff) = *reinterpret_cast<uint4*>(ph);
            *reinterpret_cast<uint4*>(ab + TILE_BYTES + boff) = *reinterpret_cast<uint4*>(pl);
        }
        __syncthreads();

        // stage next A chunk
        if (ch < 31) {
            const int j0 = (ch+1)*64;
#pragma unroll
            for (int q = 0; q < 8; q++)
                fA[q] = *reinterpret_cast<const float4*>(Asrc + (size_t)arow*SEQ + j0 + ahalf*32 + q*4);
        }

        char* vb = smem + 2*PVBUFA + (ch&1)*PVBUFV;
        hmma_3pass<4>(ab, ab + TILE_BYTES, vb, vb + BTILE64, i0w, d0w, gid, tig, acc);
        __syncthreads();

        if (ch < 30) {
            char* nvb = smem + 2*PVBUFA + (ch&1)*PVBUFV;
            const int j0 = (ch+2)*64;
            cp_tile64(nvb,           Bh + j0, SEQ, tid);
            cp_tile64(nvb + BTILE64, Bl + j0, SEQ, tid);
            CP_COMMIT();
        }
    }

#pragma unroll
    for (int nt = 0; nt < 4; nt++) {
        const int d = d0w + nt*8 + tig*2;
#pragma unroll
        for (int mt = 0; mt < 2; mt++) {
#pragma unroll
            for (int half = 0; half < 2; half++) {
                const int row = m0 + i0w + mt*16 + gid + half*8;
                float v0 = acc[mt][nt][half*2+0];
                float v1 = acc[mt][nt][half*2+1];
                __nv_bfloat16 h0,l0,h1,l1;
                bf16_split(v0,h0,l0); bf16_split(v1,h1,l1);
                size_t o = ((size_t)(b*SEQ + row))*D_MODEL + h*DH + d;
                *reinterpret_cast<uint32_t*>(g_Xh + o) = pack2(h0,h1);
                *reinterpret_cast<uint32_t*>(g_Xl + o) = pack2(l0,l1);
            }
        }
    }
}

// ---------------------------------------------------------------------------
extern "C" void kernel_launch(void* const* d_in, const int* in_sizes, int n_in,
                              void* d_out, int out_size)
{
    const float* query = (const float*)d_in[0];
    const float* key   = (const float*)d_in[1];
    const float* value = (const float*)d_in[2];
    const int*   mask  = (const int*)  d_in[3];
    const float* Wq    = (const float*)d_in[4];
    const float* bq    = (const float*)d_in[5];
    const float* Wk    = (const float*)d_in[6];
    const float* bk    = (const float*)d_in[7];
    const float* Wv    = (const float*)d_in[8];
    const float* bv    = (const float*)d_in[9];
    const float* Wo    = (const float*)d_in[10];
    const float* bo    = (const float*)d_in[11];

    float* out = (float*)d_out;
    float* attn_arg = ((long long)out_size >= (long long)OUT_ELEMS + ATTN_ELEMS)
                      ? (out + OUT_ELEMS) : nullptr;

    cudaFuncSetAttribute(qkv_proj_kernel,   cudaFuncAttributeMaxDynamicSharedMemorySize, PROJ_SMEM);
    cudaFuncSetAttribute(oproj_kernel,      cudaFuncAttributeMaxDynamicSharedMemorySize, PROJ_SMEM);
    cudaFuncSetAttribute(fused_attn_kernel, cudaFuncAttributeMaxDynamicSharedMemorySize, FUSED_SMEM);
    cudaFuncSetAttribute(pv_kernel,         cudaFuncAttributeMaxDynamicSharedMemorySize, PV_SMEM);

    dim3 blk(256);
    split_kernel     <<<dim3(256, 7), blk>>>(query, key, value, Wq, Wk, Wv, Wo);
    qkv_proj_kernel  <<<dim3(4, 32, 3), blk, PROJ_SMEM>>>(bq, bk, bv);
    fused_attn_kernel<<<dim3(128, 16), blk, FUSED_SMEM>>>(mask, attn_arg);
    pv_kernel        <<<dim3(16, 16), blk, PV_SMEM>>>(attn_arg);
    oproj_kernel     <<<dim3(4, 32), blk, PROJ_SMEM>>>(bo, out);
}

// round 6
// speedup vs baseline: 1.0858x; 1.0858x over previous
#include <cuda_runtime.h>
#include <cuda_bf16.h>
#include <cstdint>
#include <cstddef>

#define D_MODEL 512
#define NHEAD   8
#define DH      64
#define BATCH   2
#define SEQ     2048
#define NTOK    (BATCH*SEQ)   // 4096
#define NBH     (BATCH*NHEAD) // 16
#define N1      (NTOK*D_MODEL)     // 2,097,152
#define N2      (D_MODEL*D_MODEL)  // 262,144

static const int       OUT_ELEMS  = N1;
static const long long ATTN_ELEMS = (long long)NBH*SEQ*SEQ;

// ---------------- device scratch (allocation-free rule) ----------------
__device__ __align__(16) __nv_bfloat16 g_INh[3*N1], g_INl[3*N1];
__device__ __align__(16) __nv_bfloat16 g_Wh[4*N2],  g_Wl[4*N2];
__device__ __align__(16) __nv_bfloat16 g_Qh[NBH*SEQ*DH], g_Ql[NBH*SEQ*DH];
__device__ __align__(16) __nv_bfloat16 g_Kh[NBH*SEQ*DH], g_Kl[NBH*SEQ*DH];
__device__ __align__(16) __nv_bfloat16 g_Vth[NBH*DH*SEQ], g_Vtl[NBH*DH*SEQ];
__device__ __align__(16) __nv_bfloat16 g_Xh[N1], g_Xl[N1];
__device__ __align__(16) float         g_attn_fallback[(size_t)NBH*SEQ*SEQ];

// ---------------- helpers ----------------
__device__ __forceinline__ uint32_t smem_u32(const void* p) {
    uint32_t a;
    asm("{ .reg .u64 t; cvta.to.shared.u64 t, %1; cvt.u32.u64 %0, t; }" : "=r"(a) : "l"(p));
    return a;
}
__device__ __forceinline__ void bf16_split(float v, __nv_bfloat16& hi, __nv_bfloat16& lo) {
    hi = __float2bfloat16(v);
    lo = __float2bfloat16(v - __bfloat162float(hi));
}
__device__ __forceinline__ uint32_t pack2(__nv_bfloat16 a, __nv_bfloat16 b) {
    return (uint32_t)__bfloat16_as_ushort(a) | ((uint32_t)__bfloat16_as_ushort(b) << 16);
}
__device__ __forceinline__ void mma_bf16(float d[4], const uint32_t a[4], const uint32_t b[2]) {
    asm volatile(
        "mma.sync.aligned.m16n8k16.row.col.f32.bf16.bf16.f32 "
        "{%0,%1,%2,%3}, {%4,%5,%6,%7}, {%8,%9}, {%0,%1,%2,%3};\n"
        : "+f"(d[0]), "+f"(d[1]), "+f"(d[2]), "+f"(d[3])
        : "r"(a[0]), "r"(a[1]), "r"(a[2]), "r"(a[3]), "r"(b[0]), "r"(b[1]));
}

#define TSTRIDE_B 144
#define TILE_BYTES (128*TSTRIDE_B)    // 18432
#define BTILE64    (64*TSTRIDE_B)     // 9216

#define CP_COMMIT() asm volatile("cp.async.commit_group;" ::: "memory")

__device__ __forceinline__ void cp_tile128(char* dst, const __nv_bfloat16* src, int ld, int tid) {
    const int row = tid >> 3, c = tid & 7;
#pragma unroll
    for (int t = 0; t < 4; t++) {
        uint32_t d = smem_u32(dst + (row + t*32)*TSTRIDE_B + c*16);
        const void* g = src + (size_t)(row + t*32)*ld + c*8;
        asm volatile("cp.async.cg.shared.global [%0], [%1], 16;" :: "r"(d), "l"(g) : "memory");
    }
}
__device__ __forceinline__ void cp_tile64(char* dst, const __nv_bfloat16* src, int ld, int tid) {
    const int row = tid >> 3, c = tid & 7;
#pragma unroll
    for (int t = 0; t < 2; t++) {
        uint32_t d = smem_u32(dst + (row + t*32)*TSTRIDE_B + c*16);
        const void* g = src + (size_t)(row + t*32)*ld + c*8;
        asm volatile("cp.async.cg.shared.global [%0], [%1], 16;" :: "r"(d), "l"(g) : "memory");
    }
}

template<int NT>
__device__ __forceinline__ void hmma_3pass(
    const char* A0, const char* A1, const char* B0, const char* B1,
    int i0w, int j0w, int gid, int tig, float acc[2][NT][4])
{
#pragma unroll
    for (int pass = 0; pass < 3; pass++) {
        const char* A = (pass == 2) ? A1 : A0;
        const char* B = (pass == 1) ? B1 : B0;
#pragma unroll
        for (int ks = 0; ks < 4; ks++) {
            const int kb = (ks*16 + tig*2) * 2;
            uint32_t a[2][4];
#pragma unroll
            for (int mt = 0; mt < 2; mt++) {
                const char* base = A + (i0w + mt*16 + gid)*TSTRIDE_B + kb;
                a[mt][0] = *reinterpret_cast<const uint32_t*>(base);
                a[mt][1] = *reinterpret_cast<const uint32_t*>(base + 8*TSTRIDE_B);
                a[mt][2] = *reinterpret_cast<const uint32_t*>(base + 16);
                a[mt][3] = *reinterpret_cast<const uint32_t*>(base + 8*TSTRIDE_B + 16);
            }
#pragma unroll
            for (int nt = 0; nt < NT; nt++) {
                const char* base = B + (j0w + nt*8 + gid)*TSTRIDE_B + kb;
                uint32_t bb[2];
                bb[0] = *reinterpret_cast<const uint32_t*>(base);
                bb[1] = *reinterpret_cast<const uint32_t*>(base + 16);
                mma_bf16(acc[0][nt], a[0], bb);
                mma_bf16(acc[1][nt], a[1], bb);
            }
        }
    }
}

// ---------------------------------------------------------------------------
// Split kernel
// ---------------------------------------------------------------------------
__global__ void __launch_bounds__(256)
split_kernel(const float* __restrict__ q, const float* __restrict__ k, const float* __restrict__ v,
             const float* __restrict__ Wq, const float* __restrict__ Wk,
             const float* __restrict__ Wv, const float* __restrict__ Wo)
{
    const int which = blockIdx.y;
    const float* src; __nv_bfloat16* dh; __nv_bfloat16* dl; int count;
    if (which < 3) {
        src = (which == 0) ? q : (which == 1) ? k : v;
        dh = g_INh + (size_t)which*N1; dl = g_INl + (size_t)which*N1; count = N1/4;
    } else {
        const int w = which - 3;
        src = (w == 0) ? Wq : (w == 1) ? Wk : (w == 2) ? Wv : Wo;
        dh = g_Wh + (size_t)w*N2; dl = g_Wl + (size_t)w*N2; count = N2/4;
    }
    for (int i = blockIdx.x*blockDim.x + threadIdx.x; i < count; i += gridDim.x*blockDim.x) {
        float4 x = reinterpret_cast<const float4*>(src)[i];
        __nv_bfloat16 h0,l0,h1,l1,h2,l2,h3,l3;
        bf16_split(x.x,h0,l0); bf16_split(x.y,h1,l1);
        bf16_split(x.z,h2,l2); bf16_split(x.w,h3,l3);
        uint2 ph, pl;
        ph.x = pack2(h0,h1); ph.y = pack2(h2,h3);
        pl.x = pack2(l0,l1); pl.y = pack2(l2,l3);
        reinterpret_cast<uint2*>(dh)[i] = ph;
        reinterpret_cast<uint2*>(dl)[i] = pl;
    }
}

// ---------------------------------------------------------------------------
// QKV projection (R4, unchanged)
// ---------------------------------------------------------------------------
#define PROJ_SMEM (8*TILE_BYTES)   // 147456
__global__ void __launch_bounds__(256)
qkv_proj_kernel(const float* __restrict__ bq, const float* __restrict__ bk,
                const float* __restrict__ bv)
{
    extern __shared__ char smem[];
    const int tid = threadIdx.x, wid = tid >> 5, lane = tid & 31;
    const int gid = lane >> 2, tig = lane & 3;
    const int z = blockIdx.z;
    const int m0 = blockIdx.y*128, n0 = blockIdx.x*128;
    const int i0w = (wid & 3)*32, j0w = (wid >> 2)*64;

    const __nv_bfloat16* Ah = g_INh + (size_t)z*N1 + (size_t)m0*D_MODEL;
    const __nv_bfloat16* Al = g_INl + (size_t)z*N1 + (size_t)m0*D_MODEL;
    const __nv_bfloat16* Bh = g_Wh  + (size_t)z*N2 + (size_t)n0*D_MODEL;
    const __nv_bfloat16* Bl = g_Wl  + (size_t)z*N2 + (size_t)n0*D_MODEL;
    const float* bias = (z == 0) ? bq : (z == 1) ? bk : bv;

    float acc[2][8][4];
#pragma unroll
    for (int mt = 0; mt < 2; mt++)
#pragma unroll
        for (int nt = 0; nt < 8; nt++)
#pragma unroll
            for (int q = 0; q < 4; q++) acc[mt][nt][q] = 0.f;

    {
        char* buf = smem;
        cp_tile128(buf,                Ah, D_MODEL, tid);
        cp_tile128(buf +   TILE_BYTES, Al, D_MODEL, tid);
        cp_tile128(buf + 2*TILE_BYTES, Bh, D_MODEL, tid);
        cp_tile128(buf + 3*TILE_BYTES, Bl, D_MODEL, tid);
        CP_COMMIT();
    }
    for (int ch = 0; ch < 8; ch++) {
        if (ch < 7) {
            char* buf = smem + ((ch+1)&1)*(4*TILE_BYTES);
            const int k0 = (ch+1)*64;
            cp_tile128(buf,                Ah + k0, D_MODEL, tid);
            cp_tile128(buf +   TILE_BYTES, Al + k0, D_MODEL, tid);
            cp_tile128(buf + 2*TILE_BYTES, Bh + k0, D_MODEL, tid);
            cp_tile128(buf + 3*TILE_BYTES, Bl + k0, D_MODEL, tid);
            CP_COMMIT();
            asm volatile("cp.async.wait_group 1;" ::: "memory");
        } else {
            asm volatile("cp.async.wait_group 0;" ::: "memory");
        }
        __syncthreads();
        char* buf = smem + (ch&1)*(4*TILE_BYTES);
        hmma_3pass<8>(buf, buf + TILE_BYTES, buf + 2*TILE_BYTES, buf + 3*TILE_BYTES,
                      i0w, j0w, gid, tig, acc);
        __syncthreads();
    }

#pragma unroll
    for (int nt = 0; nt < 8; nt++) {
        const int col = n0 + j0w + nt*8 + tig*2;
        const int h = col >> 6, d = col & 63;
        const float b0v = bias[col], b1v = bias[col+1];
#pragma unroll
        for (int mt = 0; mt < 2; mt++) {
#pragma unroll
            for (int half = 0; half < 2; half++) {
                const int token = m0 + i0w + mt*16 + gid + half*8;
                const int b = token >> 11, s = token & 2047;
                float v0 = acc[mt][nt][half*2+0] + b0v;
                float v1 = acc[mt][nt][half*2+1] + b1v;
                __nv_bfloat16 h0,l0,h1,l1;
                bf16_split(v0,h0,l0); bf16_split(v1,h1,l1);
                if (z == 0) {
                    size_t o = ((size_t)(b*NHEAD + h)*SEQ + s)*DH + d;
                    *reinterpret_cast<uint32_t*>(g_Qh + o) = pack2(h0,h1);
                    *reinterpret_cast<uint32_t*>(g_Ql + o) = pack2(l0,l1);
                } else if (z == 1) {
                    size_t o = ((size_t)(b*NHEAD + h)*SEQ + s)*DH + d;
                    *reinterpret_cast<uint32_t*>(g_Kh + o) = pack2(h0,h1);
                    *reinterpret_cast<uint32_t*>(g_Kl + o) = pack2(l0,l1);
                } else {
                    size_t o0 = ((size_t)(b*NHEAD + h)*DH + d)*SEQ + s;
                    g_Vth[o0] = h0; g_Vtl[o0] = l0;
                    g_Vth[o0 + SEQ] = h1; g_Vtl[o0 + SEQ] = l1;
                }
            }
        }
    }
}

// ---------------------------------------------------------------------------
// Output projection (R4, unchanged)
// ---------------------------------------------------------------------------
__global__ void __launch_bounds__(256)
oproj_kernel(const float* __restrict__ bo, float* __restrict__ out)
{
    extern __shared__ char smem[];
    const int tid = threadIdx.x, wid = tid >> 5, lane = tid & 31;
    const int gid = lane >> 2, tig = lane & 3;
    const int m0 = blockIdx.y*128, n0 = blockIdx.x*128;
    const int i0w = (wid & 3)*32, j0w = (wid >> 2)*64;

    const __nv_bfloat16* Ah = g_Xh + (size_t)m0*D_MODEL;
    const __nv_bfloat16* Al = g_Xl + (size_t)m0*D_MODEL;
    const __nv_bfloat16* Bh = g_Wh + (size_t)3*N2 + (size_t)n0*D_MODEL;
    const __nv_bfloat16* Bl = g_Wl + (size_t)3*N2 + (size_t)n0*D_MODEL;

    float acc[2][8][4];
#pragma unroll
    for (int mt = 0; mt < 2; mt++)
#pragma unroll
        for (int nt = 0; nt < 8; nt++)
#pragma unroll
            for (int q = 0; q < 4; q++) acc[mt][nt][q] = 0.f;

    {
        char* buf = smem;
        cp_tile128(buf,                Ah, D_MODEL, tid);
        cp_tile128(buf +   TILE_BYTES, Al, D_MODEL, tid);
        cp_tile128(buf + 2*TILE_BYTES, Bh, D_MODEL, tid);
        cp_tile128(buf + 3*TILE_BYTES, Bl, D_MODEL, tid);
        CP_COMMIT();
    }
    for (int ch = 0; ch < 8; ch++) {
        if (ch < 7) {
            char* buf = smem + ((ch+1)&1)*(4*TILE_BYTES);
            const int k0 = (ch+1)*64;
            cp_tile128(buf,                Ah + k0, D_MODEL, tid);
            cp_tile128(buf +   TILE_BYTES, Al + k0, D_MODEL, tid);
            cp_tile128(buf + 2*TILE_BYTES, Bh + k0, D_MODEL, tid);
            cp_tile128(buf + 3*TILE_BYTES, Bl + k0, D_MODEL, tid);
            CP_COMMIT();
            asm volatile("cp.async.wait_group 1;" ::: "memory");
        } else {
            asm volatile("cp.async.wait_group 0;" ::: "memory");
        }
        __syncthreads();
        char* buf = smem + (ch&1)*(4*TILE_BYTES);
        hmma_3pass<8>(buf, buf + TILE_BYTES, buf + 2*TILE_BYTES, buf + 3*TILE_BYTES,
                      i0w, j0w, gid, tig, acc);
        __syncthreads();
    }

#pragma unroll
    for (int nt = 0; nt < 8; nt++) {
        const int col = n0 + j0w + nt*8 + tig*2;
        const float b0v = bo[col], b1v = bo[col+1];
#pragma unroll
        for (int mt = 0; mt < 2; mt++) {
#pragma unroll
            for (int half = 0; half < 2; half++) {
                const int row = m0 + i0w + mt*16 + gid + half*8;
                float2 o;
                o.x = acc[mt][nt][half*2+0] + b0v;
                o.y = acc[mt][nt][half*2+1] + b1v;
                *reinterpret_cast<float2*>(out + (size_t)row*D_MODEL + col) = o;
            }
        }
    }
}

// ---------------------------------------------------------------------------
// Score kernel (R4, unchanged): writes masked+scaled scores fp32 to attn.
// ---------------------------------------------------------------------------
#define SCORE_SMEM (4*TILE_BYTES)
__global__ void __launch_bounds__(256)
score_kernel(const int* __restrict__ mask, float* attn_arg)
{
    float* attn = attn_arg ? attn_arg : g_attn_fallback;
    extern __shared__ char smem[];
    char* sQ0 = smem;
    char* sQ1 = smem + TILE_BYTES;
    char* sK0 = smem + 2*TILE_BYTES;
    char* sK1 = smem + 3*TILE_BYTES;

    const int tid = threadIdx.x, wid = tid >> 5, lane = tid & 31;
    const int gid = lane >> 2, tig = lane & 3;
    const int bh = blockIdx.z, b = bh >> 3;
    const int m0 = blockIdx.y*128, n0 = blockIdx.x*128;
    const int i0w = (wid & 3)*32, j0w = (wid >> 2)*64;

    cp_tile128(sQ0, g_Qh + ((size_t)bh*SEQ + m0)*DH, DH, tid);
    cp_tile128(sQ1, g_Ql + ((size_t)bh*SEQ + m0)*DH, DH, tid);
    cp_tile128(sK0, g_Kh + ((size_t)bh*SEQ + n0)*DH, DH, tid);
    cp_tile128(sK1, g_Kl + ((size_t)bh*SEQ + n0)*DH, DH, tid);
    CP_COMMIT();
    asm volatile("cp.async.wait_group 0;" ::: "memory");
    __syncthreads();

    float acc[2][8][4];
#pragma unroll
    for (int mt = 0; mt < 2; mt++)
#pragma unroll
        for (int nt = 0; nt < 8; nt++)
#pragma unroll
            for (int q = 0; q < 4; q++) acc[mt][nt][q] = 0.f;

    hmma_3pass<8>(sQ0, sQ1, sK0, sK1, i0w, j0w, gid, tig, acc);

#pragma unroll
    for (int nt = 0; nt < 8; nt++) {
        const int col = n0 + j0w + nt*8 + tig*2;
        const int mv0 = __ldg(mask + b*SEQ + col);
        const int mv1 = __ldg(mask + b*SEQ + col + 1);
#pragma unroll
        for (int mt = 0; mt < 2; mt++) {
#pragma unroll
            for (int half = 0; half < 2; half++) {
                const int row = m0 + i0w + mt*16 + gid + half*8;
                float v0 = acc[mt][nt][half*2+0] * 0.125f;
                float v1 = acc[mt][nt][half*2+1] * 0.125f;
                if (mv0 == 0) v0 = -1.0e9f;
                if (mv1 == 0) v1 = -1.0e9f;
                float2 o; o.x = v0; o.y = v1;
                *reinterpret_cast<float2*>(attn + ((size_t)bh*SEQ + row)*SEQ + col) = o;
            }
        }
    }
}

// ---------------------------------------------------------------------------
// Fused softmax + PV: CTA = 64 q-rows x one bh. grid (32, 16) = 512 CTAs.
// Phase A: online row max / exp-sum over scores (reads attn, no stores).
// Phase B: re-read scores in 64-col chunks, p=exp(v-m)*inv, write attn once,
//          split to bf16 in smem, HMMA vs cp.async double-buffered V.
// smem: A hi (9216) + A lo (9216) + V 2x(hi+lo) (36864) + row stats (512)
// ---------------------------------------------------------------------------
#define SMPV_A0    0
#define SMPV_A1    BTILE64
#define SMPV_V     (2*BTILE64)                 // 18432
#define SMPV_STATS (2*BTILE64 + 2*2*BTILE64)   // 55296
#define SMPV_SMEM  (SMPV_STATS + 512)          // 55808
__global__ void __launch_bounds__(256)
smpv_kernel(float* attn_arg)
{
    float* attn = attn_arg ? attn_arg : g_attn_fallback;
    extern __shared__ char smem[];
    char* sA0 = smem + SMPV_A0;
    char* sA1 = smem + SMPV_A1;
    float* rowM   = reinterpret_cast<float*>(smem + SMPV_STATS);
    float* rowInv = rowM + 64;

    const int tid = threadIdx.x, wid = tid >> 5, lane = tid & 31;
    const int gid = lane >> 2, tig = lane & 3;
    const int bh = blockIdx.y, b = bh >> 3, h = bh & 7;
    const int m0 = blockIdx.x * 64;
    const int i0w = (wid & 1)*32, d0w = (wid >> 1)*16;

    const __nv_bfloat16* Bh = g_Vth + (size_t)bh*DH*SEQ;
    const __nv_bfloat16* Bl = g_Vtl + (size_t)bh*DH*SEQ;

    // issue V chunks 0,1 early (overlap with phase A)
    {
        char* vb = smem + SMPV_V;
        cp_tile64(vb,           Bh, SEQ, tid);
        cp_tile64(vb + BTILE64, Bl, SEQ, tid);
        CP_COMMIT();
        vb = smem + SMPV_V + 2*BTILE64;
        cp_tile64(vb,           Bh + 64, SEQ, tid);
        cp_tile64(vb + BTILE64, Bl + 64, SEQ, tid);
        CP_COMMIT();
    }

    // ---- Phase A: row stats (4 threads per row, 2 chains each) ----
    {
        const int row = tid >> 2, quarter = tid & 3;
        const float* Sr = attn + ((size_t)bh*SEQ + m0 + row)*SEQ + quarter*512;
        float m1 = -3.0e38f, s1 = 0.f, m2 = -3.0e38f, s2 = 0.f;
#pragma unroll 4
        for (int i = 0; i < 64; i++) {
            float4 va = *reinterpret_cast<const float4*>(Sr + i*4);
            float4 vb = *reinterpret_cast<const float4*>(Sr + 256 + i*4);
            float ma = fmaxf(fmaxf(va.x,va.y), fmaxf(va.z,va.w));
            float mb = fmaxf(fmaxf(vb.x,vb.y), fmaxf(vb.z,vb.w));
            if (ma > m1) { s1 *= __expf(m1 - ma); m1 = ma; }
            if (mb > m2) { s2 *= __expf(m2 - mb); m2 = mb; }
            s1 += __expf(va.x-m1)+__expf(va.y-m1)+__expf(va.z-m1)+__expf(va.w-m1);
            s2 += __expf(vb.x-m2)+__expf(vb.y-m2)+__expf(vb.z-m2)+__expf(vb.w-m2);
        }
        float m = fmaxf(m1, m2);
        float s = s1*__expf(m1 - m) + s2*__expf(m2 - m);
#pragma unroll
        for (int o = 1; o < 4; o <<= 1) {
            float mo = __shfl_xor_sync(0xffffffffu, m, o);
            float so = __shfl_xor_sync(0xffffffffu, s, o);
            float mn = fmaxf(m, mo);
            s = s*__expf(m - mn) + so*__expf(mo - mn);
            m = mn;
        }
        if (quarter == 0) { rowM[row] = m; rowInv[row] = 1.0f / s; }
    }
    __syncthreads();

    // ---- Phase B ----
    const int arow = tid >> 2, q4 = tid & 3;   // row 0..63, col block q4*16
    float* Sr = attn + ((size_t)bh*SEQ + m0 + arow)*SEQ + q4*16;
    const float mrow = rowM[arow];
    const float inv  = rowInv[arow];

    float acc[2][2][4];
#pragma unroll
    for (int mt = 0; mt < 2; mt++)
#pragma unroll
        for (int nt = 0; nt < 2; nt++)
#pragma unroll
            for (int q = 0; q < 4; q++) acc[mt][nt][q] = 0.f;

    float4 fA[4];
#pragma unroll
    for (int q = 0; q < 4; q++)
        fA[q] = *reinterpret_cast<const float4*>(Sr + q*4);

    for (int ch = 0; ch < 32; ch++) {
        if (ch < 30) asm volatile("cp.async.wait_group 1;" ::: "memory");
        else         asm volatile("cp.async.wait_group 0;" ::: "memory");

        // p = exp(v-m)*inv; write attn; split to bf16 smem
        {
            const int boff = arow*TSTRIDE_B + q4*32;
            uint32_t ph[8], pl[8];
#pragma unroll
            for (int q = 0; q < 4; q++) {
                float4 v = fA[q];
                v.x = __expf(v.x - mrow) * inv;
                v.y = __expf(v.y - mrow) * inv;
                v.z = __expf(v.z - mrow) * inv;
                v.w = __expf(v.w - mrow) * inv;
                *reinterpret_cast<float4*>(Sr + (size_t)ch*64 + q*4) = v;
                __nv_bfloat16 h0,l0,h1,l1,h2,l2,h3,l3;
                bf16_split(v.x,h0,l0); bf16_split(v.y,h1,l1);
                bf16_split(v.z,h2,l2); bf16_split(v.w,h3,l3);
                ph[2*q+0] = pack2(h0,h1); ph[2*q+1] = pack2(h2,h3);
                pl[2*q+0] = pack2(l0,l1); pl[2*q+1] = pack2(l2,l3);
            }
            *reinterpret_cast<uint4*>(sA0 + boff)      = *reinterpret_cast<uint4*>(ph);
            *reinterpret_cast<uint4*>(sA0 + boff + 16) = *reinterpret_cast<uint4*>(ph + 4);
            *reinterpret_cast<uint4*>(sA1 + boff)      = *reinterpret_cast<uint4*>(pl);
            *reinterpret_cast<uint4*>(sA1 + boff + 16) = *reinterpret_cast<uint4*>(pl + 4);
        }
        __syncthreads();

        // prefetch next score chunk into registers
        if (ch < 31) {
#pragma unroll
            for (int q = 0; q < 4; q++)
                fA[q] = *reinterpret_cast<const float4*>(Sr + (size_t)(ch+1)*64 + q*4);
        }

        char* vb = smem + SMPV_V + (ch&1)*(2*BTILE64);
        hmma_3pass<2>(sA0, sA1, vb, vb + BTILE64, i0w, d0w, gid, tig, acc);
        __syncthreads();

        if (ch < 30) {
            char* nvb = smem + SMPV_V + (ch&1)*(2*BTILE64);
            const int j0 = (ch+2)*64;
            cp_tile64(nvb,           Bh + j0, SEQ, tid);
            cp_tile64(nvb + BTILE64, Bl + j0, SEQ, tid);
            CP_COMMIT();
        }
    }

    // epilogue: split X to bf16 hi/lo for oproj
#pragma unroll
    for (int nt = 0; nt < 2; nt++) {
        const int d = d0w + nt*8 + tig*2;
#pragma unroll
        for (int mt = 0; mt < 2; mt++) {
#pragma unroll
            for (int half = 0; half < 2; half++) {
                const int row = m0 + i0w + mt*16 + gid + half*8;
                float v0 = acc[mt][nt][half*2+0];
                float v1 = acc[mt][nt][half*2+1];
                __nv_bfloat16 h0,l0,h1,l1;
                bf16_split(v0,h0,l0); bf16_split(v1,h1,l1);
                size_t o = ((size_t)(b*SEQ + row))*D_MODEL + h*DH + d;
                *reinterpret_cast<uint32_t*>(g_Xh + o) = pack2(h0,h1);
                *reinterpret_cast<uint32_t*>(g_Xl + o) = pack2(l0,l1);
            }
        }
    }
}

// ---------------------------------------------------------------------------
extern "C" void kernel_launch(void* const* d_in, const int* in_sizes, int n_in,
                              void* d_out, int out_size)
{
    const float* query = (const float*)d_in[0];
    const float* key   = (const float*)d_in[1];
    const float* value = (const float*)d_in[2];
    const int*   mask  = (const int*)  d_in[3];
    const float* Wq    = (const float*)d_in[4];
    const float* bq    = (const float*)d_in[5];
    const float* Wk    = (const float*)d_in[6];
    const float* bk    = (const float*)d_in[7];
    const float* Wv    = (const float*)d_in[8];
    const float* bv    = (const float*)d_in[9];
    const float* Wo    = (const float*)d_in[10];
    const float* bo    = (const float*)d_in[11];

    float* out = (float*)d_out;
    float* attn_arg = ((long long)out_size >= (long long)OUT_ELEMS + ATTN_ELEMS)
                      ? (out + OUT_ELEMS) : nullptr;

    cudaFuncSetAttribute(qkv_proj_kernel, cudaFuncAttributeMaxDynamicSharedMemorySize, PROJ_SMEM);
    cudaFuncSetAttribute(oproj_kernel,    cudaFuncAttributeMaxDynamicSharedMemorySize, PROJ_SMEM);
    cudaFuncSetAttribute(score_kernel,    cudaFuncAttributeMaxDynamicSharedMemorySize, SCORE_SMEM);
    cudaFuncSetAttribute(smpv_kernel,     cudaFuncAttributeMaxDynamicSharedMemorySize, SMPV_SMEM);

    dim3 blk(256);
    split_kernel   <<<dim3(256, 7), blk>>>(query, key, value, Wq, Wk, Wv, Wo);
    qkv_proj_kernel<<<dim3(4, 32, 3), blk, PROJ_SMEM>>>(bq, bk, bv);
    score_kernel   <<<dim3(16, 16, 16), blk, SCORE_SMEM>>>(mask, attn_arg);
    smpv_kernel    <<<dim3(32, 16), blk, SMPV_SMEM>>>(attn_arg);
    oproj_kernel   <<<dim3(4, 32), blk, PROJ_SMEM>>>(bo, out);
}

// round 7
// speedup vs baseline: 1.2032x; 1.1082x over previous
#include <cuda_runtime.h>
#include <cuda_bf16.h>
#include <cstdint>
#include <cstddef>

#define D_MODEL 512
#define NHEAD   8
#define DH      64
#define BATCH   2
#define SEQ     2048
#define NTOK    (BATCH*SEQ)   // 4096
#define NBH     (BATCH*NHEAD) // 16
#define N1      (NTOK*D_MODEL)     // 2,097,152
#define N2      (D_MODEL*D_MODEL)  // 262,144

static const int       OUT_ELEMS  = N1;
static const long long ATTN_ELEMS = (long long)NBH*SEQ*SEQ;

// ---------------- device scratch (allocation-free rule) ----------------
__device__ __align__(16) __nv_bfloat16 g_INh[3*N1], g_INl[3*N1];
__device__ __align__(16) __nv_bfloat16 g_Wh[4*N2],  g_Wl[4*N2];
__device__ __align__(16) __nv_bfloat16 g_Qh[NBH*SEQ*DH], g_Ql[NBH*SEQ*DH];
__device__ __align__(16) __nv_bfloat16 g_Kh[NBH*SEQ*DH], g_Kl[NBH*SEQ*DH];
__device__ __align__(16) __nv_bfloat16 g_Vth[NBH*DH*SEQ], g_Vtl[NBH*DH*SEQ];
__device__ __align__(16) __nv_bfloat16 g_Ah[(size_t)NBH*SEQ*SEQ], g_Al[(size_t)NBH*SEQ*SEQ];
__device__ __align__(16) __nv_bfloat16 g_Xh[N1], g_Xl[N1];
__device__ __align__(16) float         g_attn_fallback[(size_t)NBH*SEQ*SEQ];

// ---------------- helpers ----------------
__device__ __forceinline__ uint32_t smem_u32(const void* p) {
    uint32_t a;
    asm("{ .reg .u64 t; cvta.to.shared.u64 t, %1; cvt.u32.u64 %0, t; }" : "=r"(a) : "l"(p));
    return a;
}
__device__ __forceinline__ void bf16_split(float v, __nv_bfloat16& hi, __nv_bfloat16& lo) {
    hi = __float2bfloat16(v);
    lo = __float2bfloat16(v - __bfloat162float(hi));
}
__device__ __forceinline__ uint32_t pack2(__nv_bfloat16 a, __nv_bfloat16 b) {
    return (uint32_t)__bfloat16_as_ushort(a) | ((uint32_t)__bfloat16_as_ushort(b) << 16);
}
__device__ __forceinline__ void mma_bf16(float d[4], const uint32_t a[4], const uint32_t b[2]) {
    asm volatile(
        "mma.sync.aligned.m16n8k16.row.col.f32.bf16.bf16.f32 "
        "{%0,%1,%2,%3}, {%4,%5,%6,%7}, {%8,%9}, {%0,%1,%2,%3};\n"
        : "+f"(d[0]), "+f"(d[1]), "+f"(d[2]), "+f"(d[3])
        : "r"(a[0]), "r"(a[1]), "r"(a[2]), "r"(a[3]), "r"(b[0]), "r"(b[1]));
}

#define TSTRIDE_B 144
#define TILE_BYTES (128*TSTRIDE_B)    // 18432
#define BTILE64    (64*TSTRIDE_B)     // 9216

#define CP_COMMIT() asm volatile("cp.async.commit_group;" ::: "memory")

__device__ __forceinline__ void cp_tile128(char* dst, const __nv_bfloat16* src, int ld, int tid) {
    const int row = tid >> 3, c = tid & 7;
#pragma unroll
    for (int t = 0; t < 4; t++) {
        uint32_t d = smem_u32(dst + (row + t*32)*TSTRIDE_B + c*16);
        const void* g = src + (size_t)(row + t*32)*ld + c*8;
        asm volatile("cp.async.cg.shared.global [%0], [%1], 16;" :: "r"(d), "l"(g) : "memory");
    }
}
__device__ __forceinline__ void cp_tile64(char* dst, const __nv_bfloat16* src, int ld, int tid) {
    const int row = tid >> 3, c = tid & 7;
#pragma unroll
    for (int t = 0; t < 2; t++) {
        uint32_t d = smem_u32(dst + (row + t*32)*TSTRIDE_B + c*16);
        const void* g = src + (size_t)(row + t*32)*ld + c*8;
        asm volatile("cp.async.cg.shared.global [%0], [%1], 16;" :: "r"(d), "l"(g) : "memory");
    }
}

template<int NT>
__device__ __forceinline__ void hmma_3pass(
    const char* A0, const char* A1, const char* B0, const char* B1,
    int i0w, int j0w, int gid, int tig, float acc[2][NT][4])
{
#pragma unroll
    for (int pass = 0; pass < 3; pass++) {
        const char* A = (pass == 2) ? A1 : A0;
        const char* B = (pass == 1) ? B1 : B0;
#pragma unroll
        for (int ks = 0; ks < 4; ks++) {
            const int kb = (ks*16 + tig*2) * 2;
            uint32_t a[2][4];
#pragma unroll
            for (int mt = 0; mt < 2; mt++) {
                const char* base = A + (i0w + mt*16 + gid)*TSTRIDE_B + kb;
                a[mt][0] = *reinterpret_cast<const uint32_t*>(base);
                a[mt][1] = *reinterpret_cast<const uint32_t*>(base + 8*TSTRIDE_B);
                a[mt][2] = *reinterpret_cast<const uint32_t*>(base + 16);
                a[mt][3] = *reinterpret_cast<const uint32_t*>(base + 8*TSTRIDE_B + 16);
            }
#pragma unroll
            for (int nt = 0; nt < NT; nt++) {
                const char* base = B + (j0w + nt*8 + gid)*TSTRIDE_B + kb;
                uint32_t bb[2];
                bb[0] = *reinterpret_cast<const uint32_t*>(base);
                bb[1] = *reinterpret_cast<const uint32_t*>(base + 16);
                mma_bf16(acc[0][nt], a[0], bb);
                mma_bf16(acc[1][nt], a[1], bb);
            }
        }
    }
}

// ---------------------------------------------------------------------------
// Split kernel
// ---------------------------------------------------------------------------
__global__ void __launch_bounds__(256)
split_kernel(const float* __restrict__ q, const float* __restrict__ k, const float* __restrict__ v,
             const float* __restrict__ Wq, const float* __restrict__ Wk,
             const float* __restrict__ Wv, const float* __restrict__ Wo)
{
    const int which = blockIdx.y;
    const float* src; __nv_bfloat16* dh; __nv_bfloat16* dl; int count;
    if (which < 3) {
        src = (which == 0) ? q : (which == 1) ? k : v;
        dh = g_INh + (size_t)which*N1; dl = g_INl + (size_t)which*N1; count = N1/4;
    } else {
        const int w = which - 3;
        src = (w == 0) ? Wq : (w == 1) ? Wk : (w == 2) ? Wv : Wo;
        dh = g_Wh + (size_t)w*N2; dl = g_Wl + (size_t)w*N2; count = N2/4;
    }
    for (int i = blockIdx.x*blockDim.x + threadIdx.x; i < count; i += gridDim.x*blockDim.x) {
        float4 x = reinterpret_cast<const float4*>(src)[i];
        __nv_bfloat16 h0,l0,h1,l1,h2,l2,h3,l3;
        bf16_split(x.x,h0,l0); bf16_split(x.y,h1,l1);
        bf16_split(x.z,h2,l2); bf16_split(x.w,h3,l3);
        uint2 ph, pl;
        ph.x = pack2(h0,h1); ph.y = pack2(h2,h3);
        pl.x = pack2(l0,l1); pl.y = pack2(l2,l3);
        reinterpret_cast<uint2*>(dh)[i] = ph;
        reinterpret_cast<uint2*>(dl)[i] = pl;
    }
}

// ---------------------------------------------------------------------------
// QKV projection (R4, unchanged)
// ---------------------------------------------------------------------------
#define PROJ_SMEM (8*TILE_BYTES)   // 147456
__global__ void __launch_bounds__(256)
qkv_proj_kernel(const float* __restrict__ bq, const float* __restrict__ bk,
                const float* __restrict__ bv)
{
    extern __shared__ char smem[];
    const int tid = threadIdx.x, wid = tid >> 5, lane = tid & 31;
    const int gid = lane >> 2, tig = lane & 3;
    const int z = blockIdx.z;
    const int m0 = blockIdx.y*128, n0 = blockIdx.x*128;
    const int i0w = (wid & 3)*32, j0w = (wid >> 2)*64;

    const __nv_bfloat16* Ah = g_INh + (size_t)z*N1 + (size_t)m0*D_MODEL;
    const __nv_bfloat16* Al = g_INl + (size_t)z*N1 + (size_t)m0*D_MODEL;
    const __nv_bfloat16* Bh = g_Wh  + (size_t)z*N2 + (size_t)n0*D_MODEL;
    const __nv_bfloat16* Bl = g_Wl  + (size_t)z*N2 + (size_t)n0*D_MODEL;
    const float* bias = (z == 0) ? bq : (z == 1) ? bk : bv;

    float acc[2][8][4];
#pragma unroll
    for (int mt = 0; mt < 2; mt++)
#pragma unroll
        for (int nt = 0; nt < 8; nt++)
#pragma unroll
            for (int q = 0; q < 4; q++) acc[mt][nt][q] = 0.f;

    {
        char* buf = smem;
        cp_tile128(buf,                Ah, D_MODEL, tid);
        cp_tile128(buf +   TILE_BYTES, Al, D_MODEL, tid);
        cp_tile128(buf + 2*TILE_BYTES, Bh, D_MODEL, tid);
        cp_tile128(buf + 3*TILE_BYTES, Bl, D_MODEL, tid);
        CP_COMMIT();
    }
    for (int ch = 0; ch < 8; ch++) {
        if (ch < 7) {
            char* buf = smem + ((ch+1)&1)*(4*TILE_BYTES);
            const int k0 = (ch+1)*64;
            cp_tile128(buf,                Ah + k0, D_MODEL, tid);
            cp_tile128(buf +   TILE_BYTES, Al + k0, D_MODEL, tid);
            cp_tile128(buf + 2*TILE_BYTES, Bh + k0, D_MODEL, tid);
            cp_tile128(buf + 3*TILE_BYTES, Bl + k0, D_MODEL, tid);
            CP_COMMIT();
            asm volatile("cp.async.wait_group 1;" ::: "memory");
        } else {
            asm volatile("cp.async.wait_group 0;" ::: "memory");
        }
        __syncthreads();
        char* buf = smem + (ch&1)*(4*TILE_BYTES);
        hmma_3pass<8>(buf, buf + TILE_BYTES, buf + 2*TILE_BYTES, buf + 3*TILE_BYTES,
                      i0w, j0w, gid, tig, acc);
        __syncthreads();
    }

#pragma unroll
    for (int nt = 0; nt < 8; nt++) {
        const int col = n0 + j0w + nt*8 + tig*2;
        const int h = col >> 6, d = col & 63;
        const float b0v = bias[col], b1v = bias[col+1];
#pragma unroll
        for (int mt = 0; mt < 2; mt++) {
#pragma unroll
            for (int half = 0; half < 2; half++) {
                const int token = m0 + i0w + mt*16 + gid + half*8;
                const int b = token >> 11, s = token & 2047;
                float v0 = acc[mt][nt][half*2+0] + b0v;
                float v1 = acc[mt][nt][half*2+1] + b1v;
                __nv_bfloat16 h0,l0,h1,l1;
                bf16_split(v0,h0,l0); bf16_split(v1,h1,l1);
                if (z == 0) {
                    size_t o = ((size_t)(b*NHEAD + h)*SEQ + s)*DH + d;
                    *reinterpret_cast<uint32_t*>(g_Qh + o) = pack2(h0,h1);
                    *reinterpret_cast<uint32_t*>(g_Ql + o) = pack2(l0,l1);
                } else if (z == 1) {
                    size_t o = ((size_t)(b*NHEAD + h)*SEQ + s)*DH + d;
                    *reinterpret_cast<uint32_t*>(g_Kh + o) = pack2(h0,h1);
                    *reinterpret_cast<uint32_t*>(g_Kl + o) = pack2(l0,l1);
                } else {
                    size_t o0 = ((size_t)(b*NHEAD + h)*DH + d)*SEQ + s;
                    g_Vth[o0] = h0; g_Vtl[o0] = l0;
                    g_Vth[o0 + SEQ] = h1; g_Vtl[o0 + SEQ] = l1;
                }
            }
        }
    }
}

// ---------------------------------------------------------------------------
// Output projection (R4, unchanged)
// ---------------------------------------------------------------------------
__global__ void __launch_bounds__(256)
oproj_kernel(const float* __restrict__ bo, float* __restrict__ out)
{
    extern __shared__ char smem[];
    const int tid = threadIdx.x, wid = tid >> 5, lane = tid & 31;
    const int gid = lane >> 2, tig = lane & 3;
    const int m0 = blockIdx.y*128, n0 = blockIdx.x*128;
    const int i0w = (wid & 3)*32, j0w = (wid >> 2)*64;

    const __nv_bfloat16* Ah = g_Xh + (size_t)m0*D_MODEL;
    const __nv_bfloat16* Al = g_Xl + (size_t)m0*D_MODEL;
    const __nv_bfloat16* Bh = g_Wh + (size_t)3*N2 + (size_t)n0*D_MODEL;
    const __nv_bfloat16* Bl = g_Wl + (size_t)3*N2 + (size_t)n0*D_MODEL;

    float acc[2][8][4];
#pragma unroll
    for (int mt = 0; mt < 2; mt++)
#pragma unroll
        for (int nt = 0; nt < 8; nt++)
#pragma unroll
            for (int q = 0; q < 4; q++) acc[mt][nt][q] = 0.f;

    {
        char* buf = smem;
        cp_tile128(buf,                Ah, D_MODEL, tid);
        cp_tile128(buf +   TILE_BYTES, Al, D_MODEL, tid);
        cp_tile128(buf + 2*TILE_BYTES, Bh, D_MODEL, tid);
        cp_tile128(buf + 3*TILE_BYTES, Bl, D_MODEL, tid);
        CP_COMMIT();
    }
    for (int ch = 0; ch < 8; ch++) {
        if (ch < 7) {
            char* buf = smem + ((ch+1)&1)*(4*TILE_BYTES);
            const int k0 = (ch+1)*64;
            cp_tile128(buf,                Ah + k0, D_MODEL, tid);
            cp_tile128(buf +   TILE_BYTES, Al + k0, D_MODEL, tid);
            cp_tile128(buf + 2*TILE_BYTES, Bh + k0, D_MODEL, tid);
            cp_tile128(buf + 3*TILE_BYTES, Bl + k0, D_MODEL, tid);
            CP_COMMIT();
            asm volatile("cp.async.wait_group 1;" ::: "memory");
        } else {
            asm volatile("cp.async.wait_group 0;" ::: "memory");
        }
        __syncthreads();
        char* buf = smem + (ch&1)*(4*TILE_BYTES);
        hmma_3pass<8>(buf, buf + TILE_BYTES, buf + 2*TILE_BYTES, buf + 3*TILE_BYTES,
                      i0w, j0w, gid, tig, acc);
        __syncthreads();
    }

#pragma unroll
    for (int nt = 0; nt < 8; nt++) {
        const int col = n0 + j0w + nt*8 + tig*2;
        const float b0v = bo[col], b1v = bo[col+1];
#pragma unroll
        for (int mt = 0; mt < 2; mt++) {
#pragma unroll
            for (int half = 0; half < 2; half++) {
                const int row = m0 + i0w + mt*16 + gid + half*8;
                float2 o;
                o.x = acc[mt][nt][half*2+0] + b0v;
                o.y = acc[mt][nt][half*2+1] + b1v;
                *reinterpret_cast<float2*>(out + (size_t)row*D_MODEL + col) = o;
            }
        }
    }
}

// ---------------------------------------------------------------------------
// Score kernel (R4, unchanged)
// ---------------------------------------------------------------------------
#define SCORE_SMEM (4*TILE_BYTES)
__global__ void __launch_bounds__(256)
score_kernel(const int* __restrict__ mask, float* attn_arg)
{
    float* attn = attn_arg ? attn_arg : g_attn_fallback;
    extern __shared__ char smem[];
    char* sQ0 = smem;
    char* sQ1 = smem + TILE_BYTES;
    char* sK0 = smem + 2*TILE_BYTES;
    char* sK1 = smem + 3*TILE_BYTES;

    const int tid = threadIdx.x, wid = tid >> 5, lane = tid & 31;
    const int gid = lane >> 2, tig = lane & 3;
    const int bh = blockIdx.z, b = bh >> 3;
    const int m0 = blockIdx.y*128, n0 = blockIdx.x*128;
    const int i0w = (wid & 3)*32, j0w = (wid >> 2)*64;

    cp_tile128(sQ0, g_Qh + ((size_t)bh*SEQ + m0)*DH, DH, tid);
    cp_tile128(sQ1, g_Ql + ((size_t)bh*SEQ + m0)*DH, DH, tid);
    cp_tile128(sK0, g_Kh + ((size_t)bh*SEQ + n0)*DH, DH, tid);
    cp_tile128(sK1, g_Kl + ((size_t)bh*SEQ + n0)*DH, DH, tid);
    CP_COMMIT();
    asm volatile("cp.async.wait_group 0;" ::: "memory");
    __syncthreads();

    float acc[2][8][4];
#pragma unroll
    for (int mt = 0; mt < 2; mt++)
#pragma unroll
        for (int nt = 0; nt < 8; nt++)
#pragma unroll
            for (int q = 0; q < 4; q++) acc[mt][nt][q] = 0.f;

    hmma_3pass<8>(sQ0, sQ1, sK0, sK1, i0w, j0w, gid, tig, acc);

#pragma unroll
    for (int nt = 0; nt < 8; nt++) {
        const int col = n0 + j0w + nt*8 + tig*2;
        const int mv0 = __ldg(mask + b*SEQ + col);
        const int mv1 = __ldg(mask + b*SEQ + col + 1);
#pragma unroll
        for (int mt = 0; mt < 2; mt++) {
#pragma unroll
            for (int half = 0; half < 2; half++) {
                const int row = m0 + i0w + mt*16 + gid + half*8;
                float v0 = acc[mt][nt][half*2+0] * 0.125f;
                float v1 = acc[mt][nt][half*2+1] * 0.125f;
                if (mv0 == 0) v0 = -1.0e9f;
                if (mv1 == 0) v1 = -1.0e9f;
                float2 o; o.x = v0; o.y = v1;
                *reinterpret_cast<float2*>(attn + ((size_t)bh*SEQ + row)*SEQ + col) = o;
            }
        }
    }
}

// ---------------------------------------------------------------------------
// Softmax (R4, unchanged): normalize in place, emit bf16 hi/lo.
// ---------------------------------------------------------------------------
__global__ void __launch_bounds__(256)
softmax_kernel(float* attn_arg)
{
    float* attn = attn_arg ? attn_arg : g_attn_fallback;
    __shared__ float red[8];
    const size_t row = blockIdx.x;
    float* p = attn + row * (size_t)SEQ;
    const int tid = threadIdx.x;

    float4 v0 = reinterpret_cast<float4*>(p)[2*tid + 0];
    float4 v1 = reinterpret_cast<float4*>(p)[2*tid + 1];

    float m = fmaxf(fmaxf(fmaxf(v0.x,v0.y), fmaxf(v0.z,v0.w)),
                    fmaxf(fmaxf(v1.x,v1.y), fmaxf(v1.z,v1.w)));
#pragma unroll
    for (int o = 16; o; o >>= 1) m = fmaxf(m, __shfl_xor_sync(0xffffffffu, m, o));
    if ((tid & 31) == 0) red[tid >> 5] = m;
    __syncthreads();
    m = red[0];
#pragma unroll
    for (int w = 1; w < 8; w++) m = fmaxf(m, red[w]);
    __syncthreads();

    v0.x = expf(v0.x - m); v0.y = expf(v0.y - m); v0.z = expf(v0.z - m); v0.w = expf(v0.w - m);
    v1.x = expf(v1.x - m); v1.y = expf(v1.y - m); v1.z = expf(v1.z - m); v1.w = expf(v1.w - m);

    float s = v0.x + v0.y + v0.z + v0.w + v1.x + v1.y + v1.z + v1.w;
#pragma unroll
    for (int o = 16; o; o >>= 1) s += __shfl_xor_sync(0xffffffffu, s, o);
    if ((tid & 31) == 0) red[tid >> 5] = s;
    __syncthreads();
    s = red[0];
#pragma unroll
    for (int w = 1; w < 8; w++) s += red[w];

    const float inv = 1.0f / s;
    v0.x *= inv; v0.y *= inv; v0.z *= inv; v0.w *= inv;
    v1.x *= inv; v1.y *= inv; v1.z *= inv; v1.w *= inv;
    reinterpret_cast<float4*>(p)[2*tid + 0] = v0;
    reinterpret_cast<float4*>(p)[2*tid + 1] = v1;

    float vf[8] = { v0.x, v0.y, v0.z, v0.w, v1.x, v1.y, v1.z, v1.w };
    __nv_bfloat16 hb[8], lb[8];
#pragma unroll
    for (int e = 0; e < 8; e++) bf16_split(vf[e], hb[e], lb[e]);
    size_t off = row * (size_t)SEQ + tid*8;
    *reinterpret_cast<uint4*>(g_Ah + off) = *reinterpret_cast<uint4*>(hb);
    *reinterpret_cast<uint4*>(g_Al + off) = *reinterpret_cast<uint4*>(lb);
}

// ---------------------------------------------------------------------------
// PV kernel (2 CTAs/SM): A single-buffered (36 KB), V double-buffered (36 KB).
// Group schedule: V prefetched 2 chunks ahead; A(ch+1) issued once hmma(ch)
// releases the A buffer. Partner CTA hides exposed A latency.
// ---------------------------------------------------------------------------
#define PV_AB    (2*TILE_BYTES)               // 36864 (A hi + lo)
#define PV_VBUF  (2*BTILE64)                  // 18432 per V buffer (hi+lo)
#define PV_SMEM  (PV_AB + 2*PV_VBUF)          // 73728
__global__ void __launch_bounds__(256, 2)
pv_kernel()
{
    extern __shared__ char smem[];
    char* ab  = smem;                          // A hi at +0, lo at +TILE_BYTES
    char* vb0 = smem + PV_AB;
    char* vb1 = smem + PV_AB + PV_VBUF;

    const int tid = threadIdx.x, wid = tid >> 5, lane = tid & 31;
    const int gid = lane >> 2, tig = lane & 3;
    const int bh = blockIdx.y, b = bh >> 3, h = bh & 7;
    const int m0 = blockIdx.x * 128;
    const int i0w = (wid & 3)*32, d0w = (wid >> 2)*32;

    const __nv_bfloat16* Ah = g_Ah + ((size_t)bh*SEQ + m0)*SEQ;
    const __nv_bfloat16* Al = g_Al + ((size_t)bh*SEQ + m0)*SEQ;
    const __nv_bfloat16* Bh = g_Vth + (size_t)bh*DH*SEQ;
    const __nv_bfloat16* Bl = g_Vtl + (size_t)bh*DH*SEQ;

    float acc[2][4][4];
#pragma unroll
    for (int mt = 0; mt < 2; mt++)
#pragma unroll
        for (int nt = 0; nt < 4; nt++)
#pragma unroll
            for (int q = 0; q < 4; q++) acc[mt][nt][q] = 0.f;

    // pre-issue: V(0), V(1), A(0) — three groups
    cp_tile64(vb0,           Bh, SEQ, tid);
    cp_tile64(vb0 + BTILE64, Bl, SEQ, tid);
    CP_COMMIT();
    cp_tile64(vb1,           Bh + 64, SEQ, tid);
    cp_tile64(vb1 + BTILE64, Bl + 64, SEQ, tid);
    CP_COMMIT();
    cp_tile128(ab,              Ah, SEQ, tid);
    cp_tile128(ab + TILE_BYTES, Al, SEQ, tid);
    CP_COMMIT();

    for (int ch = 0; ch < 32; ch++) {
        // pending at this point: at most { V(ch+1), A(ch) } (older groups done).
        // wait_group 1 -> everything except the newest group (A(ch)) done...
        // Order of issue: V(ch+1) then A(ch), so newest == A(ch). We need A(ch)
        // done too -> wait_group 0 on last iteration semantics; use 0 when no
        // more prefetch pending would stall V. Since A(ch) is always newest,
        // wait_group 0 is required to cover it; V(ch+1) completing early is
        // harmless (it only reduces V prefetch distance by finishing sooner).
        asm volatile("cp.async.wait_group 0;" ::: "memory");
        __syncthreads();

        char* vb = (ch & 1) ? vb1 : vb0;
        hmma_3pass<4>(ab, ab + TILE_BYTES, vb, vb + BTILE64, i0w, d0w, gid, tig, acc);
        __syncthreads();

        // A buffer free -> issue next A; V buffer for ch consumed -> refill for ch+2
        if (ch < 31) {
            const int j0 = (ch+1)*64;
            cp_tile128(ab,              Ah + j0, SEQ, tid);
            cp_tile128(ab + TILE_BYTES, Al + j0, SEQ, tid);
            CP_COMMIT();
        }
        if (ch < 30) {
            const int j0 = (ch+2)*64;
            char* nvb = (ch & 1) ? vb1 : vb0;
            cp_tile64(nvb,           Bh + j0, SEQ, tid);
            cp_tile64(nvb + BTILE64, Bl + j0, SEQ, tid);
            CP_COMMIT();
        }
    }

#pragma unroll
    for (int nt = 0; nt < 4; nt++) {
        const int d = d0w + nt*8 + tig*2;
#pragma unroll
        for (int mt = 0; mt < 2; mt++) {
#pragma unroll
            for (int half = 0; half < 2; half++) {
                const int row = m0 + i0w + mt*16 + gid + half*8;
                float v0 = acc[mt][nt][half*2+0];
                float v1 = acc[mt][nt][half*2+1];
                __nv_bfloat16 h0,l0,h1,l1;
                bf16_split(v0,h0,l0); bf16_split(v1,h1,l1);
                size_t o = ((size_t)(b*SEQ + row))*D_MODEL + h*DH + d;
                *reinterpret_cast<uint32_t*>(g_Xh + o) = pack2(h0,h1);
                *reinterpret_cast<uint32_t*>(g_Xl + o) = pack2(l0,l1);
            }
        }
    }
}

// ---------------------------------------------------------------------------
extern "C" void kernel_launch(void* const* d_in, const int* in_sizes, int n_in,
                              void* d_out, int out_size)
{
    const float* query = (const float*)d_in[0];
    const float* key   = (const float*)d_in[1];
    const float* value = (const float*)d_in[2];
    const int*   mask  = (const int*)  d_in[3];
    const float* Wq    = (const float*)d_in[4];
    const float* bq    = (const float*)d_in[5];
    const float* Wk    = (const float*)d_in[6];
    const float* bk    = (const float*)d_in[7];
    const float* Wv    = (const float*)d_in[8];
    const float* bv    = (const float*)d_in[9];
    const float* Wo    = (const float*)d_in[10];
    const float* bo    = (const float*)d_in[11];

    float* out = (float*)d_out;
    float* attn_arg = ((long long)out_size >= (long long)OUT_ELEMS + ATTN_ELEMS)
                      ? (out + OUT_ELEMS) : nullptr;

    cudaFuncSetAttribute(qkv_proj_kernel, cudaFuncAttributeMaxDynamicSharedMemorySize, PROJ_SMEM);
    cudaFuncSetAttribute(oproj_kernel,    cudaFuncAttributeMaxDynamicSharedMemorySize, PROJ_SMEM);
    cudaFuncSetAttribute(score_kernel,    cudaFuncAttributeMaxDynamicSharedMemorySize, SCORE_SMEM);
    cudaFuncSetAttribute(pv_kernel,       cudaFuncAttributeMaxDynamicSharedMemorySize, PV_SMEM);

    dim3 blk(256);
    split_kernel   <<<dim3(256, 7), blk>>>(query, key, value, Wq, Wk, Wv, Wo);
    qkv_proj_kernel<<<dim3(4, 32, 3), blk, PROJ_SMEM>>>(bq, bk, bv);
    score_kernel   <<<dim3(16, 16, 16), blk, SCORE_SMEM>>>(mask, attn_arg);
    softmax_kernel <<<dim3(NBH*SEQ), blk>>>(attn_arg);
    pv_kernel      <<<dim3(16, 16), blk, PV_SMEM>>>();
    oproj_kernel   <<<dim3(4, 32), blk, PROJ_SMEM>>>(bo, out);
}

// round 8
// speedup vs baseline: 1.2315x; 1.0235x over previous
#include <cuda_runtime.h>
#include <cuda_bf16.h>
#include <cstdint>
#include <cstddef>

#define D_MODEL 512
#define NHEAD   8
#define DH      64
#define BATCH   2
#define SEQ     2048
#define NTOK    (BATCH*SEQ)   // 4096
#define NBH     (BATCH*NHEAD) // 16
#define N1      (NTOK*D_MODEL)     // 2,097,152
#define N2      (D_MODEL*D_MODEL)  // 262,144

static const int       OUT_ELEMS  = N1;
static const long long ATTN_ELEMS = (long long)NBH*SEQ*SEQ;

// ---------------- device scratch (allocation-free rule) ----------------
__device__ __align__(16) __nv_bfloat16 g_INh[3*N1], g_INl[3*N1];
__device__ __align__(16) __nv_bfloat16 g_Wh[4*N2],  g_Wl[4*N2];
__device__ __align__(16) __nv_bfloat16 g_Qh[NBH*SEQ*DH], g_Ql[NBH*SEQ*DH];
__device__ __align__(16) __nv_bfloat16 g_Kh[NBH*SEQ*DH], g_Kl[NBH*SEQ*DH];
__device__ __align__(16) __nv_bfloat16 g_Vth[NBH*DH*SEQ], g_Vtl[NBH*DH*SEQ];
__device__ __align__(16) __nv_bfloat16 g_Ah[(size_t)NBH*SEQ*SEQ], g_Al[(size_t)NBH*SEQ*SEQ];
__device__ __align__(16) __nv_bfloat16 g_Xh[N1], g_Xl[N1];
__device__ __align__(16) float         g_attn_fallback[(size_t)NBH*SEQ*SEQ];

// ---------------- helpers ----------------
__device__ __forceinline__ uint32_t smem_u32(const void* p) {
    uint32_t a;
    asm("{ .reg .u64 t; cvta.to.shared.u64 t, %1; cvt.u32.u64 %0, t; }" : "=r"(a) : "l"(p));
    return a;
}
__device__ __forceinline__ void bf16_split(float v, __nv_bfloat16& hi, __nv_bfloat16& lo) {
    hi = __float2bfloat16(v);
    lo = __float2bfloat16(v - __bfloat162float(hi));
}
__device__ __forceinline__ uint32_t pack2(__nv_bfloat16 a, __nv_bfloat16 b) {
    return (uint32_t)__bfloat16_as_ushort(a) | ((uint32_t)__bfloat16_as_ushort(b) << 16);
}
__device__ __forceinline__ void mma_bf16(float d[4], const uint32_t a[4], const uint32_t b[2]) {
    asm volatile(
        "mma.sync.aligned.m16n8k16.row.col.f32.bf16.bf16.f32 "
        "{%0,%1,%2,%3}, {%4,%5,%6,%7}, {%8,%9}, {%0,%1,%2,%3};\n"
        : "+f"(d[0]), "+f"(d[1]), "+f"(d[2]), "+f"(d[3])
        : "r"(a[0]), "r"(a[1]), "r"(a[2]), "r"(a[3]), "r"(b[0]), "r"(b[1]));
}
__device__ __forceinline__ void ldsm_x4(uint32_t& r0, uint32_t& r1, uint32_t& r2, uint32_t& r3,
                                        uint32_t addr) {
    asm volatile("ldmatrix.sync.aligned.m8n8.x4.shared.b16 {%0,%1,%2,%3}, [%4];"
        : "=r"(r0), "=r"(r1), "=r"(r2), "=r"(r3) : "r"(addr));
}

#define TSTRIDE_B 144
#define TILE_BYTES (128*TSTRIDE_B)    // 18432
#define BTILE64    (64*TSTRIDE_B)     // 9216

#define CP_COMMIT() asm volatile("cp.async.commit_group;" ::: "memory")

__device__ __forceinline__ void cp_tile128(char* dst, const __nv_bfloat16* src, int ld, int tid) {
    const int row = tid >> 3, c = tid & 7;
#pragma unroll
    for (int t = 0; t < 4; t++) {
        uint32_t d = smem_u32(dst + (row + t*32)*TSTRIDE_B + c*16);
        const void* g = src + (size_t)(row + t*32)*ld + c*8;
        asm volatile("cp.async.cg.shared.global [%0], [%1], 16;" :: "r"(d), "l"(g) : "memory");
    }
}
__device__ __forceinline__ void cp_tile64(char* dst, const __nv_bfloat16* src, int ld, int tid) {
    const int row = tid >> 3, c = tid & 7;
#pragma unroll
    for (int t = 0; t < 2; t++) {
        uint32_t d = smem_u32(dst + (row + t*32)*TSTRIDE_B + c*16);
        const void* g = src + (size_t)(row + t*32)*ld + c*8;
        asm volatile("cp.async.cg.shared.global [%0], [%1], 16;" :: "r"(d), "l"(g) : "memory");
    }
}

// ---------------------------------------------------------------------------
// 3-pass (hh + h*lo + lo*h) HMMA with ldmatrix fragment loads.
// A-row offset (per lane): row = (l&7) + ((l>>3)&1)*8, kcol16 = l>>4.
// B-row offset (per lane): row = (l&7) + ((l>>4)&1)*8, kcol16 = (l>>3)&1.
// LDSM output order == mma fragment order (verified mapping).
// ---------------------------------------------------------------------------
template<int NT>
__device__ __forceinline__ void hmma_3pass(
    const char* A0c, const char* A1c, const char* B0c, const char* B1c,
    int i0w, int j0w, int gid, int tig, float acc[2][NT][4])
{
    const int lane = (threadIdx.x & 31);
    const uint32_t aoff = (uint32_t)(((lane & 7) + ((lane >> 3) & 1)*8)*TSTRIDE_B + (lane >> 4)*16);
    const uint32_t boff = (uint32_t)(((lane & 7) + ((lane >> 4) & 1)*8)*TSTRIDE_B + ((lane >> 3) & 1)*16);
    const uint32_t A0 = smem_u32(A0c) + i0w*TSTRIDE_B + aoff;
    const uint32_t A1 = smem_u32(A1c) + i0w*TSTRIDE_B + aoff;
    const uint32_t B0 = smem_u32(B0c) + j0w*TSTRIDE_B + boff;
    const uint32_t B1 = smem_u32(B1c) + j0w*TSTRIDE_B + boff;

#pragma unroll
    for (int pass = 0; pass < 3; pass++) {
        const uint32_t A = (pass == 2) ? A1 : A0;
        const uint32_t B = (pass == 1) ? B1 : B0;
#pragma unroll
        for (int ks = 0; ks < 4; ks++) {
            uint32_t a[2][4];
#pragma unroll
            for (int mt = 0; mt < 2; mt++)
                ldsm_x4(a[mt][0], a[mt][1], a[mt][2], a[mt][3],
                        A + mt*16*TSTRIDE_B + ks*32);
#pragma unroll
            for (int p = 0; p < NT/2; p++) {
                uint32_t b0, b1, b2, b3;
                ldsm_x4(b0, b1, b2, b3, B + p*16*TSTRIDE_B + ks*32);
                uint32_t bbA[2] = { b0, b1 };
                uint32_t bbB[2] = { b2, b3 };
                mma_bf16(acc[0][2*p+0], a[0], bbA);
                mma_bf16(acc[1][2*p+0], a[1], bbA);
                mma_bf16(acc[0][2*p+1], a[0], bbB);
                mma_bf16(acc[1][2*p+1], a[1], bbB);
            }
        }
    }
}

// ---------------------------------------------------------------------------
// Split kernel
// ---------------------------------------------------------------------------
__global__ void __launch_bounds__(256)
split_kernel(const float* __restrict__ q, const float* __restrict__ k, const float* __restrict__ v,
             const float* __restrict__ Wq, const float* __restrict__ Wk,
             const float* __restrict__ Wv, const float* __restrict__ Wo)
{
    const int which = blockIdx.y;
    const float* src; __nv_bfloat16* dh; __nv_bfloat16* dl; int count;
    if (which < 3) {
        src = (which == 0) ? q : (which == 1) ? k : v;
        dh = g_INh + (size_t)which*N1; dl = g_INl + (size_t)which*N1; count = N1/4;
    } else {
        const int w = which - 3;
        src = (w == 0) ? Wq : (w == 1) ? Wk : (w == 2) ? Wv : Wo;
        dh = g_Wh + (size_t)w*N2; dl = g_Wl + (size_t)w*N2; count = N2/4;
    }
    for (int i = blockIdx.x*blockDim.x + threadIdx.x; i < count; i += gridDim.x*blockDim.x) {
        float4 x = reinterpret_cast<const float4*>(src)[i];
        __nv_bfloat16 h0,l0,h1,l1,h2,l2,h3,l3;
        bf16_split(x.x,h0,l0); bf16_split(x.y,h1,l1);
        bf16_split(x.z,h2,l2); bf16_split(x.w,h3,l3);
        uint2 ph, pl;
        ph.x = pack2(h0,h1); ph.y = pack2(h2,h3);
        pl.x = pack2(l0,l1); pl.y = pack2(l2,l3);
        reinterpret_cast<uint2*>(dh)[i] = ph;
        reinterpret_cast<uint2*>(dl)[i] = pl;
    }
}

// ---------------------------------------------------------------------------
// QKV projection: HMMA split, 128x128 tile, K=512 (8 chunks), cp.async 2-deep.
// ---------------------------------------------------------------------------
#define PROJ_SMEM (8*TILE_BYTES)   // 147456
__global__ void __launch_bounds__(256)
qkv_proj_kernel(const float* __restrict__ bq, const float* __restrict__ bk,
                const float* __restrict__ bv)
{
    extern __shared__ char smem[];
    const int tid = threadIdx.x, wid = tid >> 5, lane = tid & 31;
    const int gid = lane >> 2, tig = lane & 3;
    const int z = blockIdx.z;
    const int m0 = blockIdx.y*128, n0 = blockIdx.x*128;
    const int i0w = (wid & 3)*32, j0w = (wid >> 2)*64;

    const __nv_bfloat16* Ah = g_INh + (size_t)z*N1 + (size_t)m0*D_MODEL;
    const __nv_bfloat16* Al = g_INl + (size_t)z*N1 + (size_t)m0*D_MODEL;
    const __nv_bfloat16* Bh = g_Wh  + (size_t)z*N2 + (size_t)n0*D_MODEL;
    const __nv_bfloat16* Bl = g_Wl  + (size_t)z*N2 + (size_t)n0*D_MODEL;
    const float* bias = (z == 0) ? bq : (z == 1) ? bk : bv;

    float acc[2][8][4];
#pragma unroll
    for (int mt = 0; mt < 2; mt++)
#pragma unroll
        for (int nt = 0; nt < 8; nt++)
#pragma unroll
            for (int q = 0; q < 4; q++) acc[mt][nt][q] = 0.f;

    {
        char* buf = smem;
        cp_tile128(buf,                Ah, D_MODEL, tid);
        cp_tile128(buf +   TILE_BYTES, Al, D_MODEL, tid);
        cp_tile128(buf + 2*TILE_BYTES, Bh, D_MODEL, tid);
        cp_tile128(buf + 3*TILE_BYTES, Bl, D_MODEL, tid);
        CP_COMMIT();
    }
    for (int ch = 0; ch < 8; ch++) {
        if (ch < 7) {
            char* buf = smem + ((ch+1)&1)*(4*TILE_BYTES);
            const int k0 = (ch+1)*64;
            cp_tile128(buf,                Ah + k0, D_MODEL, tid);
            cp_tile128(buf +   TILE_BYTES, Al + k0, D_MODEL, tid);
            cp_tile128(buf + 2*TILE_BYTES, Bh + k0, D_MODEL, tid);
            cp_tile128(buf + 3*TILE_BYTES, Bl + k0, D_MODEL, tid);
            CP_COMMIT();
            asm volatile("cp.async.wait_group 1;" ::: "memory");
        } else {
            asm volatile("cp.async.wait_group 0;" ::: "memory");
        }
        __syncthreads();
        char* buf = smem + (ch&1)*(4*TILE_BYTES);
        hmma_3pass<8>(buf, buf + TILE_BYTES, buf + 2*TILE_BYTES, buf + 3*TILE_BYTES,
                      i0w, j0w, gid, tig, acc);
        __syncthreads();
    }

#pragma unroll
    for (int nt = 0; nt < 8; nt++) {
        const int col = n0 + j0w + nt*8 + tig*2;
        const int h = col >> 6, d = col & 63;
        const float b0v = bias[col], b1v = bias[col+1];
#pragma unroll
        for (int mt = 0; mt < 2; mt++) {
#pragma unroll
            for (int half = 0; half < 2; half++) {
                const int token = m0 + i0w + mt*16 + gid + half*8;
                const int b = token >> 11, s = token & 2047;
                float v0 = acc[mt][nt][half*2+0] + b0v;
                float v1 = acc[mt][nt][half*2+1] + b1v;
                __nv_bfloat16 h0,l0,h1,l1;
                bf16_split(v0,h0,l0); bf16_split(v1,h1,l1);
                if (z == 0) {
                    size_t o = ((size_t)(b*NHEAD + h)*SEQ + s)*DH + d;
                    *reinterpret_cast<uint32_t*>(g_Qh + o) = pack2(h0,h1);
                    *reinterpret_cast<uint32_t*>(g_Ql + o) = pack2(l0,l1);
                } else if (z == 1) {
                    size_t o = ((size_t)(b*NHEAD + h)*SEQ + s)*DH + d;
                    *reinterpret_cast<uint32_t*>(g_Kh + o) = pack2(h0,h1);
                    *reinterpret_cast<uint32_t*>(g_Kl + o) = pack2(l0,l1);
                } else {
                    size_t o0 = ((size_t)(b*NHEAD + h)*DH + d)*SEQ + s;
                    g_Vth[o0] = h0; g_Vtl[o0] = l0;
                    g_Vth[o0 + SEQ] = h1; g_Vtl[o0 + SEQ] = l1;
                }
            }
        }
    }
}

// ---------------------------------------------------------------------------
// Output projection
// ---------------------------------------------------------------------------
__global__ void __launch_bounds__(256)
oproj_kernel(const float* __restrict__ bo, float* __restrict__ out)
{
    extern __shared__ char smem[];
    const int tid = threadIdx.x, wid = tid >> 5, lane = tid & 31;
    const int gid = lane >> 2, tig = lane & 3;
    const int m0 = blockIdx.y*128, n0 = blockIdx.x*128;
    const int i0w = (wid & 3)*32, j0w = (wid >> 2)*64;

    const __nv_bfloat16* Ah = g_Xh + (size_t)m0*D_MODEL;
    const __nv_bfloat16* Al = g_Xl + (size_t)m0*D_MODEL;
    const __nv_bfloat16* Bh = g_Wh + (size_t)3*N2 + (size_t)n0*D_MODEL;
    const __nv_bfloat16* Bl = g_Wl + (size_t)3*N2 + (size_t)n0*D_MODEL;

    float acc[2][8][4];
#pragma unroll
    for (int mt = 0; mt < 2; mt++)
#pragma unroll
        for (int nt = 0; nt < 8; nt++)
#pragma unroll
            for (int q = 0; q < 4; q++) acc[mt][nt][q] = 0.f;

    {
        char* buf = smem;
        cp_tile128(buf,                Ah, D_MODEL, tid);
        cp_tile128(buf +   TILE_BYTES, Al, D_MODEL, tid);
        cp_tile128(buf + 2*TILE_BYTES, Bh, D_MODEL, tid);
        cp_tile128(buf + 3*TILE_BYTES, Bl, D_MODEL, tid);
        CP_COMMIT();
    }
    for (int ch = 0; ch < 8; ch++) {
        if (ch < 7) {
            char* buf = smem + ((ch+1)&1)*(4*TILE_BYTES);
            const int k0 = (ch+1)*64;
            cp_tile128(buf,                Ah + k0, D_MODEL, tid);
            cp_tile128(buf +   TILE_BYTES, Al + k0, D_MODEL, tid);
            cp_tile128(buf + 2*TILE_BYTES, Bh + k0, D_MODEL, tid);
            cp_tile128(buf + 3*TILE_BYTES, Bl + k0, D_MODEL, tid);
            CP_COMMIT();
            asm volatile("cp.async.wait_group 1;" ::: "memory");
        } else {
            asm volatile("cp.async.wait_group 0;" ::: "memory");
        }
        __syncthreads();
        char* buf = smem + (ch&1)*(4*TILE_BYTES);
        hmma_3pass<8>(buf, buf + TILE_BYTES, buf + 2*TILE_BYTES, buf + 3*TILE_BYTES,
                      i0w, j0w, gid, tig, acc);
        __syncthreads();
    }

#pragma unroll
    for (int nt = 0; nt < 8; nt++) {
        const int col = n0 + j0w + nt*8 + tig*2;
        const float b0v = bo[col], b1v = bo[col+1];
#pragma unroll
        for (int mt = 0; mt < 2; mt++) {
#pragma unroll
            for (int half = 0; half < 2; half++) {
                const int row = m0 + i0w + mt*16 + gid + half*8;
                float2 o;
                o.x = acc[mt][nt][half*2+0] + b0v;
                o.y = acc[mt][nt][half*2+1] + b1v;
                *reinterpret_cast<float2*>(out + (size_t)row*D_MODEL + col) = o;
            }
        }
    }
}

// ---------------------------------------------------------------------------
// Score kernel
// ---------------------------------------------------------------------------
#define SCORE_SMEM (4*TILE_BYTES)
__global__ void __launch_bounds__(256)
score_kernel(const int* __restrict__ mask, float* attn_arg)
{
    float* attn = attn_arg ? attn_arg : g_attn_fallback;
    extern __shared__ char smem[];
    char* sQ0 = smem;
    char* sQ1 = smem + TILE_BYTES;
    char* sK0 = smem + 2*TILE_BYTES;
    char* sK1 = smem + 3*TILE_BYTES;

    const int tid = threadIdx.x, wid = tid >> 5, lane = tid & 31;
    const int gid = lane >> 2, tig = lane & 3;
    const int bh = blockIdx.z, b = bh >> 3;
    const int m0 = blockIdx.y*128, n0 = blockIdx.x*128;
    const int i0w = (wid & 3)*32, j0w = (wid >> 2)*64;

    cp_tile128(sQ0, g_Qh + ((size_t)bh*SEQ + m0)*DH, DH, tid);
    cp_tile128(sQ1, g_Ql + ((size_t)bh*SEQ + m0)*DH, DH, tid);
    cp_tile128(sK0, g_Kh + ((size_t)bh*SEQ + n0)*DH, DH, tid);
    cp_tile128(sK1, g_Kl + ((size_t)bh*SEQ + n0)*DH, DH, tid);
    CP_COMMIT();
    asm volatile("cp.async.wait_group 0;" ::: "memory");
    __syncthreads();

    float acc[2][8][4];
#pragma unroll
    for (int mt = 0; mt < 2; mt++)
#pragma unroll
        for (int nt = 0; nt < 8; nt++)
#pragma unroll
            for (int q = 0; q < 4; q++) acc[mt][nt][q] = 0.f;

    hmma_3pass<8>(sQ0, sQ1, sK0, sK1, i0w, j0w, gid, tig, acc);

#pragma unroll
    for (int nt = 0; nt < 8; nt++) {
        const int col = n0 + j0w + nt*8 + tig*2;
        const int mv0 = __ldg(mask + b*SEQ + col);
        const int mv1 = __ldg(mask + b*SEQ + col + 1);
#pragma unroll
        for (int mt = 0; mt < 2; mt++) {
#pragma unroll
            for (int half = 0; half < 2; half++) {
                const int row = m0 + i0w + mt*16 + gid + half*8;
                float v0 = acc[mt][nt][half*2+0] * 0.125f;
                float v1 = acc[mt][nt][half*2+1] * 0.125f;
                if (mv0 == 0) v0 = -1.0e9f;
                if (mv1 == 0) v1 = -1.0e9f;
                float2 o; o.x = v0; o.y = v1;
                *reinterpret_cast<float2*>(attn + ((size_t)bh*SEQ + row)*SEQ + col) = o;
            }
        }
    }
}

// ---------------------------------------------------------------------------
// Softmax: per-row, normalize in place, emit bf16 hi/lo.
// ---------------------------------------------------------------------------
__global__ void __launch_bounds__(256)
softmax_kernel(float* attn_arg)
{
    float* attn = attn_arg ? attn_arg : g_attn_fallback;
    __shared__ float red[8];
    const size_t row = blockIdx.x;
    float* p = attn + row * (size_t)SEQ;
    const int tid = threadIdx.x;

    float4 v0 = reinterpret_cast<float4*>(p)[2*tid + 0];
    float4 v1 = reinterpret_cast<float4*>(p)[2*tid + 1];

    float m = fmaxf(fmaxf(fmaxf(v0.x,v0.y), fmaxf(v0.z,v0.w)),
                    fmaxf(fmaxf(v1.x,v1.y), fmaxf(v1.z,v1.w)));
#pragma unroll
    for (int o = 16; o; o >>= 1) m = fmaxf(m, __shfl_xor_sync(0xffffffffu, m, o));
    if ((tid & 31) == 0) red[tid >> 5] = m;
    __syncthreads();
    m = red[0];
#pragma unroll
    for (int w = 1; w < 8; w++) m = fmaxf(m, red[w]);
    __syncthreads();

    v0.x = __expf(v0.x - m); v0.y = __expf(v0.y - m);
    v0.z = __expf(v0.z - m); v0.w = __expf(v0.w - m);
    v1.x = __expf(v1.x - m); v1.y = __expf(v1.y - m);
    v1.z = __expf(v1.z - m); v1.w = __expf(v1.w - m);

    float s = v0.x + v0.y + v0.z + v0.w + v1.x + v1.y + v1.z + v1.w;
#pragma unroll
    for (int o = 16; o; o >>= 1) s += __shfl_xor_sync(0xffffffffu, s, o);
    if ((tid & 31) == 0) red[tid >> 5] = s;
    __syncthreads();
    s = red[0];
#pragma unroll
    for (int w = 1; w < 8; w++) s += red[w];

    const float inv = 1.0f / s;
    v0.x *= inv; v0.y *= inv; v0.z *= inv; v0.w *= inv;
    v1.x *= inv; v1.y *= inv; v1.z *= inv; v1.w *= inv;
    reinterpret_cast<float4*>(p)[2*tid + 0] = v0;
    reinterpret_cast<float4*>(p)[2*tid + 1] = v1;

    float vf[8] = { v0.x, v0.y, v0.z, v0.w, v1.x, v1.y, v1.z, v1.w };
    __nv_bfloat16 hb[8], lb[8];
#pragma unroll
    for (int e = 0; e < 8; e++) bf16_split(vf[e], hb[e], lb[e]);
    size_t off = row * (size_t)SEQ + tid*8;
    *reinterpret_cast<uint4*>(g_Ah + off) = *reinterpret_cast<uint4*>(hb);
    *reinterpret_cast<uint4*>(g_Al + off) = *reinterpret_cast<uint4*>(lb);
}

// ---------------------------------------------------------------------------
// PV kernel (R4 structure): A+V double-buffered cp.async, 128x64 per CTA.
// ---------------------------------------------------------------------------
#define PVBUF   (2*TILE_BYTES + 2*BTILE64)   // 55296
#define PV_SMEM (2*PVBUF)                     // 110592
__global__ void __launch_bounds__(256)
pv_kernel()
{
    extern __shared__ char smem[];
    const int tid = threadIdx.x, wid = tid >> 5, lane = tid & 31;
    const int gid = lane >> 2, tig = lane & 3;
    const int bh = blockIdx.y, b = bh >> 3, h = bh & 7;
    const int m0 = blockIdx.x * 128;
    const int i0w = (wid & 3)*32, d0w = (wid >> 2)*32;

    const __nv_bfloat16* Ah = g_Ah + ((size_t)bh*SEQ + m0)*SEQ;
    const __nv_bfloat16* Al = g_Al + ((size_t)bh*SEQ + m0)*SEQ;
    const __nv_bfloat16* Bh = g_Vth + (size_t)bh*DH*SEQ;
    const __nv_bfloat16* Bl = g_Vtl + (size_t)bh*DH*SEQ;

    float acc[2][4][4];
#pragma unroll
    for (int mt = 0; mt < 2; mt++)
#pragma unroll
        for (int nt = 0; nt < 4; nt++)
#pragma unroll
            for (int q = 0; q < 4; q++) acc[mt][nt][q] = 0.f;

    {
        char* buf = smem;
        cp_tile128(buf,                         Ah, SEQ, tid);
        cp_tile128(buf + TILE_BYTES,            Al, SEQ, tid);
        cp_tile64 (buf + 2*TILE_BYTES,           Bh, SEQ, tid);
        cp_tile64 (buf + 2*TILE_BYTES + BTILE64, Bl, SEQ, tid);
        CP_COMMIT();
    }
    for (int ch = 0; ch < 32; ch++) {
        if (ch < 31) {
            char* buf = smem + ((ch+1)&1)*PVBUF;
            const int j0 = (ch+1)*64;
            cp_tile128(buf,                         Ah + j0, SEQ, tid);
            cp_tile128(buf + TILE_BYTES,            Al + j0, SEQ, tid);
            cp_tile64 (buf + 2*TILE_BYTES,           Bh + j0, SEQ, tid);
            cp_tile64 (buf + 2*TILE_BYTES + BTILE64, Bl + j0, SEQ, tid);
            CP_COMMIT();
            asm volatile("cp.async.wait_group 1;" ::: "memory");
        } else {
            asm volatile("cp.async.wait_group 0;" ::: "memory");
        }
        __syncthreads();
        char* buf = smem + (ch&1)*PVBUF;
        hmma_3pass<4>(buf, buf + TILE_BYTES, buf + 2*TILE_BYTES, buf + 2*TILE_BYTES + BTILE64,
                      i0w, d0w, gid, tig, acc);
        __syncthreads();
    }

#pragma unroll
    for (int nt = 0; nt < 4; nt++) {
        const int d = d0w + nt*8 + tig*2;
#pragma unroll
        for (int mt = 0; mt < 2; mt++) {
#pragma unroll
            for (int half = 0; half < 2; half++) {
                const int row = m0 + i0w + mt*16 + gid + half*8;
                float v0 = acc[mt][nt][half*2+0];
                float v1 = acc[mt][nt][half*2+1];
                __nv_bfloat16 h0,l0,h1,l1;
                bf16_split(v0,h0,l0); bf16_split(v1,h1,l1);
                size_t o = ((size_t)(b*SEQ + row))*D_MODEL + h*DH + d;
                *reinterpret_cast<uint32_t*>(g_Xh + o) = pack2(h0,h1);
                *reinterpret_cast<uint32_t*>(g_Xl + o) = pack2(l0,l1);
            }
        }
    }
}

// ---------------------------------------------------------------------------
extern "C" void kernel_launch(void* const* d_in, const int* in_sizes, int n_in,
                              void* d_out, int out_size)
{
    const float* query = (const float*)d_in[0];
    const float* key   = (const float*)d_in[1];
    const float* value = (const float*)d_in[2];
    const int*   mask  = (const int*)  d_in[3];
    const float* Wq    = (const float*)d_in[4];
    const float* bq    = (const float*)d_in[5];
    const float* Wk    = (const float*)d_in[6];
    const float* bk    = (const float*)d_in[7];
    const float* Wv    = (const float*)d_in[8];
    const float* bv    = (const float*)d_in[9];
    const float* Wo    = (const float*)d_in[10];
    const float* bo    = (const float*)d_in[11];

    float* out = (float*)d_out;
    float* attn_arg = ((long long)out_size >= (long long)OUT_ELEMS + ATTN_ELEMS)
                      ? (out + OUT_ELEMS) : nullptr;

    cudaFuncSetAttribute(qkv_proj_kernel, cudaFuncAttributeMaxDynamicSharedMemorySize, PROJ_SMEM);
    cudaFuncSetAttribute(oproj_kernel,    cudaFuncAttributeMaxDynamicSharedMemorySize, PROJ_SMEM);
    cudaFuncSetAttribute(score_kernel,    cudaFuncAttributeMaxDynamicSharedMemorySize, SCORE_SMEM);
    cudaFuncSetAttribute(pv_kernel,       cudaFuncAttributeMaxDynamicSharedMemorySize, PV_SMEM);

    dim3 blk(256);
    split_kernel   <<<dim3(256, 7), blk>>>(query, key, value, Wq, Wk, Wv, Wo);
    qkv_proj_kernel<<<dim3(4, 32, 3), blk, PROJ_SMEM>>>(bq, bk, bv);
    score_kernel   <<<dim3(16, 16, 16), blk, SCORE_SMEM>>>(mask, attn_arg);
    softmax_kernel <<<dim3(NBH*SEQ), blk>>>(attn_arg);
    pv_kernel      <<<dim3(16, 16), blk, PV_SMEM>>>();
    oproj_kernel   <<<dim3(4, 32), blk, PROJ_SMEM>>>(bo, out);
}